// round 5
// baseline (speedup 1.0000x reference)
#include <cuda_runtime.h>
#include <math.h>

#define NN 4096
#define KN 48
#define CC 128
#define EC 384
#define HD 512

// ---------------- scratch (device globals: allocation-free) ----------------
__device__ float g_node_pre[NN * CC];   // node @ W1a^T + b_m1
__device__ float g_S[NN * CC];          // sum_k attn * h2
__device__ float g_A[NN];               // sum_k attn
__device__ float g_X[NN * CC];          // post-LN1 x
__device__ float g_H[NN * HD];          // gelu(x @ Wd1^T + bd1)

__device__ __forceinline__ float gelu_f(float x) {
    return 0.5f * x * (1.0f + erff(x * 0.70710678118654752440f));
}

// ======================= K0: node_pre = node @ W1a^T + b1 ==================
// M=4096 (32 rows/block), N=128, K=128
__global__ __launch_bounds__(256)
void k0_node_pre(const float* __restrict__ node, const float* __restrict__ W1,
                 const float* __restrict__ b1) {
    extern __shared__ float sm[];
    float* sX = sm;           // 32*128
    float* sW = sm + 4096;    // 128*128  sW[k][c] = W1[c*512 + k]
    const int tid = threadIdx.x, tx = tid & 15, ty = tid >> 4;
    const int n0 = blockIdx.x * 32;

#pragma unroll
    for (int m = 0; m < 4; ++m) {
        int f4 = tid + 256 * m;              // 0..1023
        int r = f4 >> 5, c4 = f4 & 31;
        *(float4*)(sX + r * 128 + c4 * 4) =
            *(const float4*)(node + (size_t)(n0 + r) * 128 + c4 * 4);
    }
#pragma unroll
    for (int m = 0; m < 16; ++m) {
        int idx = tid + 256 * m;             // 0..4095
        int c = idx & 127, k4 = idx >> 7;
        float4 v = *(const float4*)(W1 + (size_t)c * 512 + k4 * 4);
        sW[(k4 * 4 + 0) * 128 + c] = v.x;
        sW[(k4 * 4 + 1) * 128 + c] = v.y;
        sW[(k4 * 4 + 2) * 128 + c] = v.z;
        sW[(k4 * 4 + 3) * 128 + c] = v.w;
    }
    __syncthreads();

    float acc[2][8] = {};
#pragma unroll
    for (int kk = 0; kk < 128; kk += 4) {
        float a[2][4];
#pragma unroll
        for (int i = 0; i < 2; ++i) {
            float4 t = *(float4*)(sX + (ty + 16 * i) * 128 + kk);
            a[i][0] = t.x; a[i][1] = t.y; a[i][2] = t.z; a[i][3] = t.w;
        }
#pragma unroll
        for (int q = 0; q < 4; ++q) {
            float4 b0 = *(float4*)(sW + (kk + q) * 128 + tx * 8);
            float4 b1v = *(float4*)(sW + (kk + q) * 128 + tx * 8 + 4);
            float bb[8] = {b0.x, b0.y, b0.z, b0.w, b1v.x, b1v.y, b1v.z, b1v.w};
#pragma unroll
            for (int i = 0; i < 2; ++i)
#pragma unroll
                for (int j = 0; j < 8; ++j) acc[i][j] += a[i][q] * bb[j];
        }
    }
#pragma unroll
    for (int i = 0; i < 2; ++i) {
        int r = n0 + ty + 16 * i;
#pragma unroll
        for (int j = 0; j < 8; ++j) {
            int c = tx * 8 + j;
            g_node_pre[(size_t)r * 128 + c] = acc[i][j] + b1[c];
        }
    }
}

// ======================= K1: per-node edge message kernel ===================
// block = one node n. GEMM1b (48x384 @ 384x128) + gelu, GEMM2 (48x128 @ 128x128)
// + gelu, attn-weighted reduce over 48 -> g_S, g_A.
__global__ __launch_bounds__(256, 2)
void k1_edges(const float* __restrict__ edge, const float* __restrict__ attn,
              const float* __restrict__ W1, const float* __restrict__ W2,
              const float* __restrict__ b2) {
    extern __shared__ float sm[];
    float* sU = sm;                 // 16384 floats: union{sA,sB} / sB2
    float* sH = sm + 16384;         // 6144: h1 (48x128), later sPart
    float* sNP = sm + 16384 + 6144; // 128
    float* sAt = sNP + 128;         // 64 (48 used)
    float* sA = sU;                 // 48*64
    float* sB = sU + 3072;          // 64*128

    const int n = blockIdx.x;
    const int tid = threadIdx.x;
    const int tx = tid & 15;
    const int ty = tid >> 4;
    const float* eb = edge + (size_t)n * (KN * EC);

    if (tid < 128) sNP[tid] = g_node_pre[(size_t)n * 128 + tid];
    if (tid < KN) sAt[tid] = attn[(size_t)n * KN + tid];

    float acc[3][8] = {};

    // ---- GEMM1b over edge context, k-tiles of 64 ----
    for (int kt = 0; kt < 6; ++kt) {
        __syncthreads();
#pragma unroll
        for (int m = 0; m < 3; ++m) {
            int f4 = tid + 256 * m;          // 0..767
            int r = f4 >> 4, c4 = f4 & 15;
            *(float4*)(sA + r * 64 + c4 * 4) =
                *(const float4*)(eb + (size_t)r * EC + kt * 64 + c4 * 4);
        }
#pragma unroll
        for (int m = 0; m < 8; ++m) {
            int idx = tid + 256 * m;         // 0..2047
            int c = idx & 127, d4 = idx >> 7;
            float4 v = *(const float4*)(W1 + (size_t)c * 512 + 128 + kt * 64 + d4 * 4);
            sB[(d4 * 4 + 0) * 128 + c] = v.x;
            sB[(d4 * 4 + 1) * 128 + c] = v.y;
            sB[(d4 * 4 + 2) * 128 + c] = v.z;
            sB[(d4 * 4 + 3) * 128 + c] = v.w;
        }
        __syncthreads();
#pragma unroll
        for (int kk = 0; kk < 64; kk += 4) {
            float a[3][4];
#pragma unroll
            for (int i = 0; i < 3; ++i) {
                float4 t = *(float4*)(sA + (ty + 16 * i) * 64 + kk);
                a[i][0] = t.x; a[i][1] = t.y; a[i][2] = t.z; a[i][3] = t.w;
            }
#pragma unroll
            for (int q = 0; q < 4; ++q) {
                float4 b0 = *(float4*)(sB + (kk + q) * 128 + tx * 8);
                float4 b1v = *(float4*)(sB + (kk + q) * 128 + tx * 8 + 4);
                float bb[8] = {b0.x, b0.y, b0.z, b0.w, b1v.x, b1v.y, b1v.z, b1v.w};
#pragma unroll
                for (int i = 0; i < 3; ++i)
#pragma unroll
                    for (int j = 0; j < 8; ++j) acc[i][j] += a[i][q] * bb[j];
            }
        }
    }

    // ---- epilogue 1: h1 = gelu(node_pre + acc) -> sH ----
#pragma unroll
    for (int i = 0; i < 3; ++i) {
        int r = ty + 16 * i;
        float h[8];
#pragma unroll
        for (int j = 0; j < 8; ++j) h[j] = gelu_f(acc[i][j] + sNP[tx * 8 + j]);
        *(float4*)(sH + r * 128 + tx * 8) = make_float4(h[0], h[1], h[2], h[3]);
        *(float4*)(sH + r * 128 + tx * 8 + 4) = make_float4(h[4], h[5], h[6], h[7]);
    }
    __syncthreads();

    // ---- load W2^T into sU: sU[c][d] = W2[d*128 + c] ----
#pragma unroll
    for (int m = 0; m < 16; ++m) {
        int idx = tid + 256 * m;             // 0..4095
        int d = idx & 127, c4 = idx >> 7;
        float4 v = *(const float4*)(W2 + (size_t)d * 128 + c4 * 4);
        sU[(c4 * 4 + 0) * 128 + d] = v.x;
        sU[(c4 * 4 + 1) * 128 + d] = v.y;
        sU[(c4 * 4 + 2) * 128 + d] = v.z;
        sU[(c4 * 4 + 3) * 128 + d] = v.w;
    }
    __syncthreads();

    // ---- GEMM2: acc2 = h1 @ W2^T ----
    float acc2[3][8] = {};
#pragma unroll
    for (int kk = 0; kk < 128; kk += 4) {
        float a[3][4];
#pragma unroll
        for (int i = 0; i < 3; ++i) {
            float4 t = *(float4*)(sH + (ty + 16 * i) * 128 + kk);
            a[i][0] = t.x; a[i][1] = t.y; a[i][2] = t.z; a[i][3] = t.w;
        }
#pragma unroll
        for (int q = 0; q < 4; ++q) {
            float4 b0 = *(float4*)(sU + (kk + q) * 128 + tx * 8);
            float4 b1v = *(float4*)(sU + (kk + q) * 128 + tx * 8 + 4);
            float bb[8] = {b0.x, b0.y, b0.z, b0.w, b1v.x, b1v.y, b1v.z, b1v.w};
#pragma unroll
            for (int i = 0; i < 3; ++i)
#pragma unroll
                for (int j = 0; j < 8; ++j) acc2[i][j] += a[i][q] * bb[j];
        }
    }

    // ---- epilogue 2: h2 = gelu(acc2 + b2); weighted partial over rows ----
    float w0 = sAt[ty], w1 = sAt[ty + 16], w2 = sAt[ty + 32];
    float4 b2a = *(const float4*)(b2 + tx * 8);
    float4 b2b = *(const float4*)(b2 + tx * 8 + 4);
    float b2v[8] = {b2a.x, b2a.y, b2a.z, b2a.w, b2b.x, b2b.y, b2b.z, b2b.w};
    float part[8];
#pragma unroll
    for (int j = 0; j < 8; ++j) {
        float p0 = gelu_f(acc2[0][j] + b2v[j]);
        float p1 = gelu_f(acc2[1][j] + b2v[j]);
        float p2 = gelu_f(acc2[2][j] + b2v[j]);
        part[j] = w0 * p0 + w1 * p1 + w2 * p2;
    }
    __syncthreads();                 // all sH reads done -> reuse as sPart
    float* sPart = sH;               // 16 x 128
    *(float4*)(sPart + ty * 128 + tx * 8) = make_float4(part[0], part[1], part[2], part[3]);
    *(float4*)(sPart + ty * 128 + tx * 8 + 4) = make_float4(part[4], part[5], part[6], part[7]);
    __syncthreads();

    if (tid < 128) {
        float s = 0.f;
#pragma unroll
        for (int t = 0; t < 16; ++t) s += sPart[t * 128 + tid];
        g_S[(size_t)n * 128 + tid] = s;
    }
    if (tid == 0) {
        float s = 0.f;
#pragma unroll
        for (int k = 0; k < KN; ++k) s += sAt[k];
        g_A[n] = s;
    }
}

// ========= K2: x = LN1(node + (W3 @ S + A*b3)/30) -> g_X (fused) ===========
__global__ __launch_bounds__(256)
void k2_ln1(const float* __restrict__ node, const float* __restrict__ W3,
            const float* __restrict__ b3, const float* __restrict__ g1,
            const float* __restrict__ be1) {
    extern __shared__ float sm[];
    float* sS = sm;            // 32*128
    float* sW = sm + 4096;     // 128*128  sW[c][d] = W3[d*128 + c]
    float* sRs = sm + 20480;   // 512
    float* sRq = sm + 20992;   // 512
    const int tid = threadIdx.x, tx = tid & 15, ty = tid >> 4;
    const int n0 = blockIdx.x * 32;

#pragma unroll
    for (int m = 0; m < 4; ++m) {
        int f4 = tid + 256 * m;
        int r = f4 >> 5, c4 = f4 & 31;
        *(float4*)(sS + r * 128 + c4 * 4) =
            *(const float4*)(g_S + (size_t)(n0 + r) * 128 + c4 * 4);
    }
#pragma unroll
    for (int m = 0; m < 16; ++m) {
        int idx = tid + 256 * m;
        int d = idx & 127, c4 = idx >> 7;
        float4 v = *(const float4*)(W3 + (size_t)d * 128 + c4 * 4);
        sW[(c4 * 4 + 0) * 128 + d] = v.x;
        sW[(c4 * 4 + 1) * 128 + d] = v.y;
        sW[(c4 * 4 + 2) * 128 + d] = v.z;
        sW[(c4 * 4 + 3) * 128 + d] = v.w;
    }
    __syncthreads();

    float acc[2][8] = {};
#pragma unroll
    for (int kk = 0; kk < 128; kk += 4) {
        float a[2][4];
#pragma unroll
        for (int i = 0; i < 2; ++i) {
            float4 t = *(float4*)(sS + (ty + 16 * i) * 128 + kk);
            a[i][0] = t.x; a[i][1] = t.y; a[i][2] = t.z; a[i][3] = t.w;
        }
#pragma unroll
        for (int q = 0; q < 4; ++q) {
            float4 b0 = *(float4*)(sW + (kk + q) * 128 + tx * 8);
            float4 b1v = *(float4*)(sW + (kk + q) * 128 + tx * 8 + 4);
            float bb[8] = {b0.x, b0.y, b0.z, b0.w, b1v.x, b1v.y, b1v.z, b1v.w};
#pragma unroll
            for (int i = 0; i < 2; ++i)
#pragma unroll
                for (int j = 0; j < 8; ++j) acc[i][j] += a[i][q] * bb[j];
        }
    }

    float xv[2][8];
    float4 b30 = *(const float4*)(b3 + tx * 8);
    float4 b31 = *(const float4*)(b3 + tx * 8 + 4);
    float b3v[8] = {b30.x, b30.y, b30.z, b30.w, b31.x, b31.y, b31.z, b31.w};
#pragma unroll
    for (int i = 0; i < 2; ++i) {
        int r = ty + 16 * i, n = n0 + r;
        float As = g_A[n];
        float4 nv0 = *(const float4*)(node + (size_t)n * 128 + tx * 8);
        float4 nv1 = *(const float4*)(node + (size_t)n * 128 + tx * 8 + 4);
        float nb[8] = {nv0.x, nv0.y, nv0.z, nv0.w, nv1.x, nv1.y, nv1.z, nv1.w};
        float s = 0.f, q = 0.f;
#pragma unroll
        for (int j = 0; j < 8; ++j) {
            float v = nb[j] + (acc[i][j] + As * b3v[j]) * (1.0f / 30.0f);
            xv[i][j] = v; s += v; q += v * v;
        }
        sRs[r * 16 + tx] = s;
        sRq[r * 16 + tx] = q;
    }
    __syncthreads();
    float4 ga = *(const float4*)(g1 + tx * 8);
    float4 gb = *(const float4*)(g1 + tx * 8 + 4);
    float4 ea = *(const float4*)(be1 + tx * 8);
    float4 ebv = *(const float4*)(be1 + tx * 8 + 4);
    float gv[8] = {ga.x, ga.y, ga.z, ga.w, gb.x, gb.y, gb.z, gb.w};
    float ev[8] = {ea.x, ea.y, ea.z, ea.w, ebv.x, ebv.y, ebv.z, ebv.w};
#pragma unroll
    for (int i = 0; i < 2; ++i) {
        int r = ty + 16 * i;
        float s = 0.f, q = 0.f;
#pragma unroll
        for (int t = 0; t < 16; ++t) { s += sRs[r * 16 + t]; q += sRq[r * 16 + t]; }
        float mu = s * (1.0f / 128.0f);
        float var = q * (1.0f / 128.0f) - mu * mu;
        float rs = rsqrtf(var + 1e-5f);
        float o[8];
#pragma unroll
        for (int j = 0; j < 8; ++j) o[j] = (xv[i][j] - mu) * rs * gv[j] + ev[j];
        *(float4*)(g_X + (size_t)(n0 + r) * 128 + tx * 8) = make_float4(o[0], o[1], o[2], o[3]);
        *(float4*)(g_X + (size_t)(n0 + r) * 128 + tx * 8 + 4) = make_float4(o[4], o[5], o[6], o[7]);
    }
}

// ================= K3: g_H = gelu(g_X @ Wd1^T + bd1)  (N=512) ===============
__global__ __launch_bounds__(256)
void k3_mlp1(const float* __restrict__ Wd1, const float* __restrict__ bd1) {
    extern __shared__ float sm[];
    float* sX = sm;          // 32*128
    float* sW = sm + 4096;   // 128*128 per n-tile: sW[k][h] = Wd1[(h0+h)*128 + k]
    const int tid = threadIdx.x, tx = tid & 15, ty = tid >> 4;
    const int n0 = blockIdx.x * 32;

#pragma unroll
    for (int m = 0; m < 4; ++m) {
        int f4 = tid + 256 * m;
        int r = f4 >> 5, c4 = f4 & 31;
        *(float4*)(sX + r * 128 + c4 * 4) =
            *(const float4*)(g_X + (size_t)(n0 + r) * 128 + c4 * 4);
    }

    for (int h0 = 0; h0 < 512; h0 += 128) {
        __syncthreads();
#pragma unroll
        for (int m = 0; m < 16; ++m) {
            int idx = tid + 256 * m;
            int h = idx & 127, k4 = idx >> 7;
            float4 v = *(const float4*)(Wd1 + (size_t)(h0 + h) * 128 + k4 * 4);
            sW[(k4 * 4 + 0) * 128 + h] = v.x;
            sW[(k4 * 4 + 1) * 128 + h] = v.y;
            sW[(k4 * 4 + 2) * 128 + h] = v.z;
            sW[(k4 * 4 + 3) * 128 + h] = v.w;
        }
        __syncthreads();
        float acc[2][8] = {};
#pragma unroll
        for (int kk = 0; kk < 128; kk += 4) {
            float a[2][4];
#pragma unroll
            for (int i = 0; i < 2; ++i) {
                float4 t = *(float4*)(sX + (ty + 16 * i) * 128 + kk);
                a[i][0] = t.x; a[i][1] = t.y; a[i][2] = t.z; a[i][3] = t.w;
            }
#pragma unroll
            for (int q = 0; q < 4; ++q) {
                float4 b0 = *(float4*)(sW + (kk + q) * 128 + tx * 8);
                float4 b1v = *(float4*)(sW + (kk + q) * 128 + tx * 8 + 4);
                float bb[8] = {b0.x, b0.y, b0.z, b0.w, b1v.x, b1v.y, b1v.z, b1v.w};
#pragma unroll
                for (int i = 0; i < 2; ++i)
#pragma unroll
                    for (int j = 0; j < 8; ++j) acc[i][j] += a[i][q] * bb[j];
            }
        }
#pragma unroll
        for (int i = 0; i < 2; ++i) {
            int r = n0 + ty + 16 * i;
#pragma unroll
            for (int j = 0; j < 8; ++j) {
                int h = h0 + tx * 8 + j;
                g_H[(size_t)r * 512 + h] = gelu_f(acc[i][j] + bd1[h]);
            }
        }
    }
}

// ===== K4: out = mask * LN2(g_X + g_H @ Wd2^T + bd2)  (K=512, N=128) ========
__global__ __launch_bounds__(256)
void k4_out(const float* __restrict__ Wd2, const float* __restrict__ bd2,
            const float* __restrict__ g2, const float* __restrict__ be2,
            const float* __restrict__ maskp, float* __restrict__ out) {
    extern __shared__ float sm[];
    float* sA = sm;            // 32*128 (k-tile of g_H)
    float* sW = sm + 4096;     // 128*128: sW[k][c] = Wd2[c*512 + k0 + k]
    float* sRs = sm + 20480;   // 512
    float* sRq = sm + 20992;   // 512
    const int tid = threadIdx.x, tx = tid & 15, ty = tid >> 4;
    const int n0 = blockIdx.x * 32;

    float acc[2][8] = {};
    for (int k0 = 0; k0 < 512; k0 += 128) {
        __syncthreads();
#pragma unroll
        for (int m = 0; m < 4; ++m) {
            int f4 = tid + 256 * m;
            int r = f4 >> 5, c4 = f4 & 31;
            *(float4*)(sA + r * 128 + c4 * 4) =
                *(const float4*)(g_H + (size_t)(n0 + r) * 512 + k0 + c4 * 4);
        }
#pragma unroll
        for (int m = 0; m < 16; ++m) {
            int idx = tid + 256 * m;
            int c = idx & 127, k4 = idx >> 7;
            float4 v = *(const float4*)(Wd2 + (size_t)c * 512 + k0 + k4 * 4);
            sW[(k4 * 4 + 0) * 128 + c] = v.x;
            sW[(k4 * 4 + 1) * 128 + c] = v.y;
            sW[(k4 * 4 + 2) * 128 + c] = v.z;
            sW[(k4 * 4 + 3) * 128 + c] = v.w;
        }
        __syncthreads();
#pragma unroll
        for (int kk = 0; kk < 128; kk += 4) {
            float a[2][4];
#pragma unroll
            for (int i = 0; i < 2; ++i) {
                float4 t = *(float4*)(sA + (ty + 16 * i) * 128 + kk);
                a[i][0] = t.x; a[i][1] = t.y; a[i][2] = t.z; a[i][3] = t.w;
            }
#pragma unroll
            for (int q = 0; q < 4; ++q) {
                float4 b0 = *(float4*)(sW + (kk + q) * 128 + tx * 8);
                float4 b1v = *(float4*)(sW + (kk + q) * 128 + tx * 8 + 4);
                float bb[8] = {b0.x, b0.y, b0.z, b0.w, b1v.x, b1v.y, b1v.z, b1v.w};
#pragma unroll
                for (int i = 0; i < 2; ++i)
#pragma unroll
                    for (int j = 0; j < 8; ++j) acc[i][j] += a[i][q] * bb[j];
            }
        }
    }

    float xv[2][8];
    float4 ba = *(const float4*)(bd2 + tx * 8);
    float4 bbv = *(const float4*)(bd2 + tx * 8 + 4);
    float bdv[8] = {ba.x, ba.y, ba.z, ba.w, bbv.x, bbv.y, bbv.z, bbv.w};
#pragma unroll
    for (int i = 0; i < 2; ++i) {
        int r = ty + 16 * i, n = n0 + r;
        float4 x0 = *(const float4*)(g_X + (size_t)n * 128 + tx * 8);
        float4 x1 = *(const float4*)(g_X + (size_t)n * 128 + tx * 8 + 4);
        float xb[8] = {x0.x, x0.y, x0.z, x0.w, x1.x, x1.y, x1.z, x1.w};
        float s = 0.f, q = 0.f;
#pragma unroll
        for (int j = 0; j < 8; ++j) {
            float v = xb[j] + acc[i][j] + bdv[j];
            xv[i][j] = v; s += v; q += v * v;
        }
        sRs[r * 16 + tx] = s;
        sRq[r * 16 + tx] = q;
    }
    __syncthreads();
    float4 ga = *(const float4*)(g2 + tx * 8);
    float4 gb = *(const float4*)(g2 + tx * 8 + 4);
    float4 ea = *(const float4*)(be2 + tx * 8);
    float4 ebv = *(const float4*)(be2 + tx * 8 + 4);
    float gv[8] = {ga.x, ga.y, ga.z, ga.w, gb.x, gb.y, gb.z, gb.w};
    float ev[8] = {ea.x, ea.y, ea.z, ea.w, ebv.x, ebv.y, ebv.z, ebv.w};
#pragma unroll
    for (int i = 0; i < 2; ++i) {
        int r = ty + 16 * i, n = n0 + r;
        float s = 0.f, q = 0.f;
#pragma unroll
        for (int t = 0; t < 16; ++t) { s += sRs[r * 16 + t]; q += sRq[r * 16 + t]; }
        float mu = s * (1.0f / 128.0f);
        float var = q * (1.0f / 128.0f) - mu * mu;
        float rs = rsqrtf(var + 1e-5f);
        float mk = maskp[n];
        float o[8];
#pragma unroll
        for (int j = 0; j < 8; ++j)
            o[j] = mk * ((xv[i][j] - mu) * rs * gv[j] + ev[j]);
        *(float4*)(out + (size_t)n * 128 + tx * 8) = make_float4(o[0], o[1], o[2], o[3]);
        *(float4*)(out + (size_t)n * 128 + tx * 8 + 4) = make_float4(o[4], o[5], o[6], o[7]);
    }
}

// ============================== launch =====================================
extern "C" void kernel_launch(void* const* d_in, const int* in_sizes, int n_in,
                              void* d_out, int out_size) {
    const float* node = (const float*)d_in[0];
    const float* edge = (const float*)d_in[1];
    const float* mask = (const float*)d_in[2];
    const float* attn = (const float*)d_in[3];
    const float* W1   = (const float*)d_in[4];
    const float* b1   = (const float*)d_in[5];
    const float* W2   = (const float*)d_in[6];
    const float* b2   = (const float*)d_in[7];
    const float* W3   = (const float*)d_in[8];
    const float* b3   = (const float*)d_in[9];
    const float* g1   = (const float*)d_in[10];
    const float* be1  = (const float*)d_in[11];
    const float* Wd1  = (const float*)d_in[12];
    const float* bd1  = (const float*)d_in[13];
    const float* Wd2  = (const float*)d_in[14];
    const float* bd2  = (const float*)d_in[15];
    const float* g2   = (const float*)d_in[16];
    const float* be2  = (const float*)d_in[17];
    float* out = (float*)d_out;

    const size_t s0 = (size_t)(4096 + 16384) * sizeof(float);
    const size_t s1 = (size_t)(16384 + 6144 + 128 + 64) * sizeof(float);
    const size_t s2 = (size_t)(4096 + 16384 + 512 + 512) * sizeof(float);
    const size_t s3 = (size_t)(4096 + 16384) * sizeof(float);
    const size_t s4 = (size_t)(4096 + 16384 + 512 + 512) * sizeof(float);

    cudaFuncSetAttribute(k0_node_pre, cudaFuncAttributeMaxDynamicSharedMemorySize, (int)s0);
    cudaFuncSetAttribute(k1_edges,    cudaFuncAttributeMaxDynamicSharedMemorySize, (int)s1);
    cudaFuncSetAttribute(k2_ln1,      cudaFuncAttributeMaxDynamicSharedMemorySize, (int)s2);
    cudaFuncSetAttribute(k3_mlp1,     cudaFuncAttributeMaxDynamicSharedMemorySize, (int)s3);
    cudaFuncSetAttribute(k4_out,      cudaFuncAttributeMaxDynamicSharedMemorySize, (int)s4);

    k0_node_pre<<<NN / 32, 256, s0>>>(node, W1, b1);
    k1_edges<<<NN, 256, s1>>>(edge, attn, W1, W2, b2);
    k2_ln1<<<NN / 32, 256, s2>>>(node, W3, b3, g1, be1);
    k3_mlp1<<<NN / 32, 256, s3>>>(Wd1, bd1);
    k4_out<<<NN / 32, 256, s4>>>(Wd2, bd2, g2, be2, mask, out);
}

// round 6
// speedup vs baseline: 1.0003x; 1.0003x over previous
#include <cuda_runtime.h>
#include <math.h>

#define NN 4096
#define KN 48
#define CC 128
#define EC 384
#define HD 512

// ---------------- scratch (device globals: allocation-free) ----------------
__device__ float g_node_pre[NN * CC];   // node @ W1a^T + b_m1
__device__ float g_S[NN * CC];          // sum_k attn * h2
__device__ float g_A[NN];               // sum_k attn
__device__ float g_X[NN * CC];          // post-LN1 x
__device__ float g_H[NN * HD];          // gelu(x @ Wd1^T + bd1)

__device__ __forceinline__ float gelu_f(float x) {
    return 0.5f * x * (1.0f + erff(x * 0.70710678118654752440f));
}

// ======================= K0: node_pre = node @ W1a^T + b1 ==================
// M=4096 (32 rows/block), N=128, K=128
__global__ __launch_bounds__(256)
void k0_node_pre(const float* __restrict__ node, const float* __restrict__ W1,
                 const float* __restrict__ b1) {
    extern __shared__ float sm[];
    float* sX = sm;           // 32*128
    float* sW = sm + 4096;    // 128*128  sW[k][c] = W1[c*512 + k]
    const int tid = threadIdx.x, tx = tid & 15, ty = tid >> 4;
    const int n0 = blockIdx.x * 32;

#pragma unroll
    for (int m = 0; m < 4; ++m) {
        int f4 = tid + 256 * m;              // 0..1023
        int r = f4 >> 5, c4 = f4 & 31;
        *(float4*)(sX + r * 128 + c4 * 4) =
            *(const float4*)(node + (size_t)(n0 + r) * 128 + c4 * 4);
    }
#pragma unroll
    for (int m = 0; m < 16; ++m) {
        int idx = tid + 256 * m;             // 0..4095
        int c = idx & 127, k4 = idx >> 7;
        float4 v = *(const float4*)(W1 + (size_t)c * 512 + k4 * 4);
        sW[(k4 * 4 + 0) * 128 + c] = v.x;
        sW[(k4 * 4 + 1) * 128 + c] = v.y;
        sW[(k4 * 4 + 2) * 128 + c] = v.z;
        sW[(k4 * 4 + 3) * 128 + c] = v.w;
    }
    __syncthreads();

    float acc[2][8] = {};
#pragma unroll
    for (int kk = 0; kk < 128; kk += 4) {
        float a[2][4];
#pragma unroll
        for (int i = 0; i < 2; ++i) {
            float4 t = *(float4*)(sX + (ty + 16 * i) * 128 + kk);
            a[i][0] = t.x; a[i][1] = t.y; a[i][2] = t.z; a[i][3] = t.w;
        }
#pragma unroll
        for (int q = 0; q < 4; ++q) {
            float4 b0 = *(float4*)(sW + (kk + q) * 128 + tx * 8);
            float4 b1v = *(float4*)(sW + (kk + q) * 128 + tx * 8 + 4);
            float bb[8] = {b0.x, b0.y, b0.z, b0.w, b1v.x, b1v.y, b1v.z, b1v.w};
#pragma unroll
            for (int i = 0; i < 2; ++i)
#pragma unroll
                for (int j = 0; j < 8; ++j) acc[i][j] += a[i][q] * bb[j];
        }
    }
#pragma unroll
    for (int i = 0; i < 2; ++i) {
        int r = n0 + ty + 16 * i;
#pragma unroll
        for (int j = 0; j < 8; ++j) {
            int c = tx * 8 + j;
            g_node_pre[(size_t)r * 128 + c] = acc[i][j] + b1[c];
        }
    }
}

// ======================= K1: per-node edge message kernel ===================
// block = one node n. GEMM1b (48x384 @ 384x128) + gelu, GEMM2 (48x128 @ 128x128)
// + gelu, attn-weighted reduce over 48 -> g_S, g_A.
__global__ __launch_bounds__(256, 2)
void k1_edges(const float* __restrict__ edge, const float* __restrict__ attn,
              const float* __restrict__ W1, const float* __restrict__ W2,
              const float* __restrict__ b2) {
    extern __shared__ float sm[];
    float* sU = sm;                 // 16384 floats: union{sA,sB} / sB2
    float* sH = sm + 16384;         // 6144: h1 (48x128), later sPart
    float* sNP = sm + 16384 + 6144; // 128
    float* sAt = sNP + 128;         // 64 (48 used)
    float* sA = sU;                 // 48*64
    float* sB = sU + 3072;          // 64*128

    const int n = blockIdx.x;
    const int tid = threadIdx.x;
    const int tx = tid & 15;
    const int ty = tid >> 4;
    const float* eb = edge + (size_t)n * (KN * EC);

    if (tid < 128) sNP[tid] = g_node_pre[(size_t)n * 128 + tid];
    if (tid < KN) sAt[tid] = attn[(size_t)n * KN + tid];

    float acc[3][8] = {};

    // ---- GEMM1b over edge context, k-tiles of 64 ----
    for (int kt = 0; kt < 6; ++kt) {
        __syncthreads();
#pragma unroll
        for (int m = 0; m < 3; ++m) {
            int f4 = tid + 256 * m;          // 0..767
            int r = f4 >> 4, c4 = f4 & 15;
            *(float4*)(sA + r * 64 + c4 * 4) =
                *(const float4*)(eb + (size_t)r * EC + kt * 64 + c4 * 4);
        }
#pragma unroll
        for (int m = 0; m < 8; ++m) {
            int idx = tid + 256 * m;         // 0..2047
            int c = idx & 127, d4 = idx >> 7;
            float4 v = *(const float4*)(W1 + (size_t)c * 512 + 128 + kt * 64 + d4 * 4);
            sB[(d4 * 4 + 0) * 128 + c] = v.x;
            sB[(d4 * 4 + 1) * 128 + c] = v.y;
            sB[(d4 * 4 + 2) * 128 + c] = v.z;
            sB[(d4 * 4 + 3) * 128 + c] = v.w;
        }
        __syncthreads();
#pragma unroll
        for (int kk = 0; kk < 64; kk += 4) {
            float a[3][4];
#pragma unroll
            for (int i = 0; i < 3; ++i) {
                float4 t = *(float4*)(sA + (ty + 16 * i) * 64 + kk);
                a[i][0] = t.x; a[i][1] = t.y; a[i][2] = t.z; a[i][3] = t.w;
            }
#pragma unroll
            for (int q = 0; q < 4; ++q) {
                float4 b0 = *(float4*)(sB + (kk + q) * 128 + tx * 8);
                float4 b1v = *(float4*)(sB + (kk + q) * 128 + tx * 8 + 4);
                float bb[8] = {b0.x, b0.y, b0.z, b0.w, b1v.x, b1v.y, b1v.z, b1v.w};
#pragma unroll
                for (int i = 0; i < 3; ++i)
#pragma unroll
                    for (int j = 0; j < 8; ++j) acc[i][j] += a[i][q] * bb[j];
            }
        }
    }

    // ---- epilogue 1: h1 = gelu(node_pre + acc) -> sH ----
#pragma unroll
    for (int i = 0; i < 3; ++i) {
        int r = ty + 16 * i;
        float h[8];
#pragma unroll
        for (int j = 0; j < 8; ++j) h[j] = gelu_f(acc[i][j] + sNP[tx * 8 + j]);
        *(float4*)(sH + r * 128 + tx * 8) = make_float4(h[0], h[1], h[2], h[3]);
        *(float4*)(sH + r * 128 + tx * 8 + 4) = make_float4(h[4], h[5], h[6], h[7]);
    }
    __syncthreads();

    // ---- load W2^T into sU: sU[c][d] = W2[d*128 + c] ----
#pragma unroll
    for (int m = 0; m < 16; ++m) {
        int idx = tid + 256 * m;             // 0..4095
        int d = idx & 127, c4 = idx >> 7;
        float4 v = *(const float4*)(W2 + (size_t)d * 128 + c4 * 4);
        sU[(c4 * 4 + 0) * 128 + d] = v.x;
        sU[(c4 * 4 + 1) * 128 + d] = v.y;
        sU[(c4 * 4 + 2) * 128 + d] = v.z;
        sU[(c4 * 4 + 3) * 128 + d] = v.w;
    }
    __syncthreads();

    // ---- GEMM2: acc2 = h1 @ W2^T ----
    float acc2[3][8] = {};
#pragma unroll
    for (int kk = 0; kk < 128; kk += 4) {
        float a[3][4];
#pragma unroll
        for (int i = 0; i < 3; ++i) {
            float4 t = *(float4*)(sH + (ty + 16 * i) * 128 + kk);
            a[i][0] = t.x; a[i][1] = t.y; a[i][2] = t.z; a[i][3] = t.w;
        }
#pragma unroll
        for (int q = 0; q < 4; ++q) {
            float4 b0 = *(float4*)(sU + (kk + q) * 128 + tx * 8);
            float4 b1v = *(float4*)(sU + (kk + q) * 128 + tx * 8 + 4);
            float bb[8] = {b0.x, b0.y, b0.z, b0.w, b1v.x, b1v.y, b1v.z, b1v.w};
#pragma unroll
            for (int i = 0; i < 3; ++i)
#pragma unroll
                for (int j = 0; j < 8; ++j) acc2[i][j] += a[i][q] * bb[j];
        }
    }

    // ---- epilogue 2: h2 = gelu(acc2 + b2); weighted partial over rows ----
    float w0 = sAt[ty], w1 = sAt[ty + 16], w2 = sAt[ty + 32];
    float4 b2a = *(const float4*)(b2 + tx * 8);
    float4 b2b = *(const float4*)(b2 + tx * 8 + 4);
    float b2v[8] = {b2a.x, b2a.y, b2a.z, b2a.w, b2b.x, b2b.y, b2b.z, b2b.w};
    float part[8];
#pragma unroll
    for (int j = 0; j < 8; ++j) {
        float p0 = gelu_f(acc2[0][j] + b2v[j]);
        float p1 = gelu_f(acc2[1][j] + b2v[j]);
        float p2 = gelu_f(acc2[2][j] + b2v[j]);
        part[j] = w0 * p0 + w1 * p1 + w2 * p2;
    }
    __syncthreads();                 // all sH reads done -> reuse as sPart
    float* sPart = sH;               // 16 x 128
    *(float4*)(sPart + ty * 128 + tx * 8) = make_float4(part[0], part[1], part[2], part[3]);
    *(float4*)(sPart + ty * 128 + tx * 8 + 4) = make_float4(part[4], part[5], part[6], part[7]);
    __syncthreads();

    if (tid < 128) {
        float s = 0.f;
#pragma unroll
        for (int t = 0; t < 16; ++t) s += sPart[t * 128 + tid];
        g_S[(size_t)n * 128 + tid] = s;
    }
    if (tid == 0) {
        float s = 0.f;
#pragma unroll
        for (int k = 0; k < KN; ++k) s += sAt[k];
        g_A[n] = s;
    }
}

// ========= K2: x = LN1(node + (W3 @ S + A*b3)/30) -> g_X (fused) ===========
__global__ __launch_bounds__(256)
void k2_ln1(const float* __restrict__ node, const float* __restrict__ W3,
            const float* __restrict__ b3, const float* __restrict__ g1,
            const float* __restrict__ be1) {
    extern __shared__ float sm[];
    float* sS = sm;            // 32*128
    float* sW = sm + 4096;     // 128*128  sW[c][d] = W3[d*128 + c]
    float* sRs = sm + 20480;   // 512
    float* sRq = sm + 20992;   // 512
    const int tid = threadIdx.x, tx = tid & 15, ty = tid >> 4;
    const int n0 = blockIdx.x * 32;

#pragma unroll
    for (int m = 0; m < 4; ++m) {
        int f4 = tid + 256 * m;
        int r = f4 >> 5, c4 = f4 & 31;
        *(float4*)(sS + r * 128 + c4 * 4) =
            *(const float4*)(g_S + (size_t)(n0 + r) * 128 + c4 * 4);
    }
#pragma unroll
    for (int m = 0; m < 16; ++m) {
        int idx = tid + 256 * m;
        int d = idx & 127, c4 = idx >> 7;
        float4 v = *(const float4*)(W3 + (size_t)d * 128 + c4 * 4);
        sW[(c4 * 4 + 0) * 128 + d] = v.x;
        sW[(c4 * 4 + 1) * 128 + d] = v.y;
        sW[(c4 * 4 + 2) * 128 + d] = v.z;
        sW[(c4 * 4 + 3) * 128 + d] = v.w;
    }
    __syncthreads();

    float acc[2][8] = {};
#pragma unroll
    for (int kk = 0; kk < 128; kk += 4) {
        float a[2][4];
#pragma unroll
        for (int i = 0; i < 2; ++i) {
            float4 t = *(float4*)(sS + (ty + 16 * i) * 128 + kk);
            a[i][0] = t.x; a[i][1] = t.y; a[i][2] = t.z; a[i][3] = t.w;
        }
#pragma unroll
        for (int q = 0; q < 4; ++q) {
            float4 b0 = *(float4*)(sW + (kk + q) * 128 + tx * 8);
            float4 b1v = *(float4*)(sW + (kk + q) * 128 + tx * 8 + 4);
            float bb[8] = {b0.x, b0.y, b0.z, b0.w, b1v.x, b1v.y, b1v.z, b1v.w};
#pragma unroll
            for (int i = 0; i < 2; ++i)
#pragma unroll
                for (int j = 0; j < 8; ++j) acc[i][j] += a[i][q] * bb[j];
        }
    }

    float xv[2][8];
    float4 b30 = *(const float4*)(b3 + tx * 8);
    float4 b31 = *(const float4*)(b3 + tx * 8 + 4);
    float b3v[8] = {b30.x, b30.y, b30.z, b30.w, b31.x, b31.y, b31.z, b31.w};
#pragma unroll
    for (int i = 0; i < 2; ++i) {
        int r = ty + 16 * i, n = n0 + r;
        float As = g_A[n];
        float4 nv0 = *(const float4*)(node + (size_t)n * 128 + tx * 8);
        float4 nv1 = *(const float4*)(node + (size_t)n * 128 + tx * 8 + 4);
        float nb[8] = {nv0.x, nv0.y, nv0.z, nv0.w, nv1.x, nv1.y, nv1.z, nv1.w};
        float s = 0.f, q = 0.f;
#pragma unroll
        for (int j = 0; j < 8; ++j) {
            float v = nb[j] + (acc[i][j] + As * b3v[j]) * (1.0f / 30.0f);
            xv[i][j] = v; s += v; q += v * v;
        }
        sRs[r * 16 + tx] = s;
        sRq[r * 16 + tx] = q;
    }
    __syncthreads();
    float4 ga = *(const float4*)(g1 + tx * 8);
    float4 gb = *(const float4*)(g1 + tx * 8 + 4);
    float4 ea = *(const float4*)(be1 + tx * 8);
    float4 ebv = *(const float4*)(be1 + tx * 8 + 4);
    float gv[8] = {ga.x, ga.y, ga.z, ga.w, gb.x, gb.y, gb.z, gb.w};
    float ev[8] = {ea.x, ea.y, ea.z, ea.w, ebv.x, ebv.y, ebv.z, ebv.w};
#pragma unroll
    for (int i = 0; i < 2; ++i) {
        int r = ty + 16 * i;
        float s = 0.f, q = 0.f;
#pragma unroll
        for (int t = 0; t < 16; ++t) { s += sRs[r * 16 + t]; q += sRq[r * 16 + t]; }
        float mu = s * (1.0f / 128.0f);
        float var = q * (1.0f / 128.0f) - mu * mu;
        float rs = rsqrtf(var + 1e-5f);
        float o[8];
#pragma unroll
        for (int j = 0; j < 8; ++j) o[j] = (xv[i][j] - mu) * rs * gv[j] + ev[j];
        *(float4*)(g_X + (size_t)(n0 + r) * 128 + tx * 8) = make_float4(o[0], o[1], o[2], o[3]);
        *(float4*)(g_X + (size_t)(n0 + r) * 128 + tx * 8 + 4) = make_float4(o[4], o[5], o[6], o[7]);
    }
}

// ================= K3: g_H = gelu(g_X @ Wd1^T + bd1)  (N=512) ===============
__global__ __launch_bounds__(256)
void k3_mlp1(const float* __restrict__ Wd1, const float* __restrict__ bd1) {
    extern __shared__ float sm[];
    float* sX = sm;          // 32*128
    float* sW = sm + 4096;   // 128*128 per n-tile: sW[k][h] = Wd1[(h0+h)*128 + k]
    const int tid = threadIdx.x, tx = tid & 15, ty = tid >> 4;
    const int n0 = blockIdx.x * 32;

#pragma unroll
    for (int m = 0; m < 4; ++m) {
        int f4 = tid + 256 * m;
        int r = f4 >> 5, c4 = f4 & 31;
        *(float4*)(sX + r * 128 + c4 * 4) =
            *(const float4*)(g_X + (size_t)(n0 + r) * 128 + c4 * 4);
    }

    for (int h0 = 0; h0 < 512; h0 += 128) {
        __syncthreads();
#pragma unroll
        for (int m = 0; m < 16; ++m) {
            int idx = tid + 256 * m;
            int h = idx & 127, k4 = idx >> 7;
            float4 v = *(const float4*)(Wd1 + (size_t)(h0 + h) * 128 + k4 * 4);
            sW[(k4 * 4 + 0) * 128 + h] = v.x;
            sW[(k4 * 4 + 1) * 128 + h] = v.y;
            sW[(k4 * 4 + 2) * 128 + h] = v.z;
            sW[(k4 * 4 + 3) * 128 + h] = v.w;
        }
        __syncthreads();
        float acc[2][8] = {};
#pragma unroll
        for (int kk = 0; kk < 128; kk += 4) {
            float a[2][4];
#pragma unroll
            for (int i = 0; i < 2; ++i) {
                float4 t = *(float4*)(sX + (ty + 16 * i) * 128 + kk);
                a[i][0] = t.x; a[i][1] = t.y; a[i][2] = t.z; a[i][3] = t.w;
            }
#pragma unroll
            for (int q = 0; q < 4; ++q) {
                float4 b0 = *(float4*)(sW + (kk + q) * 128 + tx * 8);
                float4 b1v = *(float4*)(sW + (kk + q) * 128 + tx * 8 + 4);
                float bb[8] = {b0.x, b0.y, b0.z, b0.w, b1v.x, b1v.y, b1v.z, b1v.w};
#pragma unroll
                for (int i = 0; i < 2; ++i)
#pragma unroll
                    for (int j = 0; j < 8; ++j) acc[i][j] += a[i][q] * bb[j];
            }
        }
#pragma unroll
        for (int i = 0; i < 2; ++i) {
            int r = n0 + ty + 16 * i;
#pragma unroll
            for (int j = 0; j < 8; ++j) {
                int h = h0 + tx * 8 + j;
                g_H[(size_t)r * 512 + h] = gelu_f(acc[i][j] + bd1[h]);
            }
        }
    }
}

// ===== K4: out = mask * LN2(g_X + g_H @ Wd2^T + bd2)  (K=512, N=128) ========
__global__ __launch_bounds__(256)
void k4_out(const float* __restrict__ Wd2, const float* __restrict__ bd2,
            const float* __restrict__ g2, const float* __restrict__ be2,
            const float* __restrict__ maskp, float* __restrict__ out) {
    extern __shared__ float sm[];
    float* sA = sm;            // 32*128 (k-tile of g_H)
    float* sW = sm + 4096;     // 128*128: sW[k][c] = Wd2[c*512 + k0 + k]
    float* sRs = sm + 20480;   // 512
    float* sRq = sm + 20992;   // 512
    const int tid = threadIdx.x, tx = tid & 15, ty = tid >> 4;
    const int n0 = blockIdx.x * 32;

    float acc[2][8] = {};
    for (int k0 = 0; k0 < 512; k0 += 128) {
        __syncthreads();
#pragma unroll
        for (int m = 0; m < 4; ++m) {
            int f4 = tid + 256 * m;
            int r = f4 >> 5, c4 = f4 & 31;
            *(float4*)(sA + r * 128 + c4 * 4) =
                *(const float4*)(g_H + (size_t)(n0 + r) * 512 + k0 + c4 * 4);
        }
#pragma unroll
        for (int m = 0; m < 16; ++m) {
            int idx = tid + 256 * m;
            int c = idx & 127, k4 = idx >> 7;
            float4 v = *(const float4*)(Wd2 + (size_t)c * 512 + k0 + k4 * 4);
            sW[(k4 * 4 + 0) * 128 + c] = v.x;
            sW[(k4 * 4 + 1) * 128 + c] = v.y;
            sW[(k4 * 4 + 2) * 128 + c] = v.z;
            sW[(k4 * 4 + 3) * 128 + c] = v.w;
        }
        __syncthreads();
#pragma unroll
        for (int kk = 0; kk < 128; kk += 4) {
            float a[2][4];
#pragma unroll
            for (int i = 0; i < 2; ++i) {
                float4 t = *(float4*)(sA + (ty + 16 * i) * 128 + kk);
                a[i][0] = t.x; a[i][1] = t.y; a[i][2] = t.z; a[i][3] = t.w;
            }
#pragma unroll
            for (int q = 0; q < 4; ++q) {
                float4 b0 = *(float4*)(sW + (kk + q) * 128 + tx * 8);
                float4 b1v = *(float4*)(sW + (kk + q) * 128 + tx * 8 + 4);
                float bb[8] = {b0.x, b0.y, b0.z, b0.w, b1v.x, b1v.y, b1v.z, b1v.w};
#pragma unroll
                for (int i = 0; i < 2; ++i)
#pragma unroll
                    for (int j = 0; j < 8; ++j) acc[i][j] += a[i][q] * bb[j];
            }
        }
    }

    float xv[2][8];
    float4 ba = *(const float4*)(bd2 + tx * 8);
    float4 bbv = *(const float4*)(bd2 + tx * 8 + 4);
    float bdv[8] = {ba.x, ba.y, ba.z, ba.w, bbv.x, bbv.y, bbv.z, bbv.w};
#pragma unroll
    for (int i = 0; i < 2; ++i) {
        int r = ty + 16 * i, n = n0 + r;
        float4 x0 = *(const float4*)(g_X + (size_t)n * 128 + tx * 8);
        float4 x1 = *(const float4*)(g_X + (size_t)n * 128 + tx * 8 + 4);
        float xb[8] = {x0.x, x0.y, x0.z, x0.w, x1.x, x1.y, x1.z, x1.w};
        float s = 0.f, q = 0.f;
#pragma unroll
        for (int j = 0; j < 8; ++j) {
            float v = xb[j] + acc[i][j] + bdv[j];
            xv[i][j] = v; s += v; q += v * v;
        }
        sRs[r * 16 + tx] = s;
        sRq[r * 16 + tx] = q;
    }
    __syncthreads();
    float4 ga = *(const float4*)(g2 + tx * 8);
    float4 gb = *(const float4*)(g2 + tx * 8 + 4);
    float4 ea = *(const float4*)(be2 + tx * 8);
    float4 ebv = *(const float4*)(be2 + tx * 8 + 4);
    float gv[8] = {ga.x, ga.y, ga.z, ga.w, gb.x, gb.y, gb.z, gb.w};
    float ev[8] = {ea.x, ea.y, ea.z, ea.w, ebv.x, ebv.y, ebv.z, ebv.w};
#pragma unroll
    for (int i = 0; i < 2; ++i) {
        int r = ty + 16 * i, n = n0 + r;
        float s = 0.f, q = 0.f;
#pragma unroll
        for (int t = 0; t < 16; ++t) { s += sRs[r * 16 + t]; q += sRq[r * 16 + t]; }
        float mu = s * (1.0f / 128.0f);
        float var = q * (1.0f / 128.0f) - mu * mu;
        float rs = rsqrtf(var + 1e-5f);
        float mk = maskp[n];
        float o[8];
#pragma unroll
        for (int j = 0; j < 8; ++j)
            o[j] = mk * ((xv[i][j] - mu) * rs * gv[j] + ev[j]);
        *(float4*)(out + (size_t)n * 128 + tx * 8) = make_float4(o[0], o[1], o[2], o[3]);
        *(float4*)(out + (size_t)n * 128 + tx * 8 + 4) = make_float4(o[4], o[5], o[6], o[7]);
    }
}

// ============================== launch =====================================
extern "C" void kernel_launch(void* const* d_in, const int* in_sizes, int n_in,
                              void* d_out, int out_size) {
    const float* node = (const float*)d_in[0];
    const float* edge = (const float*)d_in[1];
    const float* mask = (const float*)d_in[2];
    const float* attn = (const float*)d_in[3];
    const float* W1   = (const float*)d_in[4];
    const float* b1   = (const float*)d_in[5];
    const float* W2   = (const float*)d_in[6];
    const float* b2   = (const float*)d_in[7];
    const float* W3   = (const float*)d_in[8];
    const float* b3   = (const float*)d_in[9];
    const float* g1   = (const float*)d_in[10];
    const float* be1  = (const float*)d_in[11];
    const float* Wd1  = (const float*)d_in[12];
    const float* bd1  = (const float*)d_in[13];
    const float* Wd2  = (const float*)d_in[14];
    const float* bd2  = (const float*)d_in[15];
    const float* g2   = (const float*)d_in[16];
    const float* be2  = (const float*)d_in[17];
    float* out = (float*)d_out;

    const size_t s0 = (size_t)(4096 + 16384) * sizeof(float);
    const size_t s1 = (size_t)(16384 + 6144 + 128 + 64) * sizeof(float);
    const size_t s2 = (size_t)(4096 + 16384 + 512 + 512) * sizeof(float);
    const size_t s3 = (size_t)(4096 + 16384) * sizeof(float);
    const size_t s4 = (size_t)(4096 + 16384 + 512 + 512) * sizeof(float);

    cudaFuncSetAttribute(k0_node_pre, cudaFuncAttributeMaxDynamicSharedMemorySize, (int)s0);
    cudaFuncSetAttribute(k1_edges,    cudaFuncAttributeMaxDynamicSharedMemorySize, (int)s1);
    cudaFuncSetAttribute(k2_ln1,      cudaFuncAttributeMaxDynamicSharedMemorySize, (int)s2);
    cudaFuncSetAttribute(k3_mlp1,     cudaFuncAttributeMaxDynamicSharedMemorySize, (int)s3);
    cudaFuncSetAttribute(k4_out,      cudaFuncAttributeMaxDynamicSharedMemorySize, (int)s4);

    k0_node_pre<<<NN / 32, 256, s0>>>(node, W1, b1);
    k1_edges<<<NN, 256, s1>>>(edge, attn, W1, W2, b2);
    k2_ln1<<<NN / 32, 256, s2>>>(node, W3, b3, g1, be1);
    k3_mlp1<<<NN / 32, 256, s3>>>(Wd1, bd1);
    k4_out<<<NN / 32, 256, s4>>>(Wd2, bd2, g2, be2, mask, out);
}

// round 7
// speedup vs baseline: 1.0017x; 1.0014x over previous
#include <cuda_runtime.h>
#include <math.h>

#define NN 4096
#define KN 48
#define CC 128
#define EC 384
#define HD 512

// ---------------- scratch (device globals: allocation-free) ----------------
__device__ float g_node_pre[NN * CC];   // node @ W1a^T + b_m1
__device__ float g_S[NN * CC];          // sum_k attn * h2
__device__ float g_A[NN];               // sum_k attn
__device__ float g_X[NN * CC];          // post-LN1 x
__device__ float g_H[NN * HD];          // gelu(x @ Wd1^T + bd1)

__device__ __forceinline__ float gelu_f(float x) {
    return 0.5f * x * (1.0f + erff(x * 0.70710678118654752440f));
}

// ======================= K0: node_pre = node @ W1a^T + b1 ==================
// M=4096 (32 rows/block), N=128, K=128
__global__ __launch_bounds__(256)
void k0_node_pre(const float* __restrict__ node, const float* __restrict__ W1,
                 const float* __restrict__ b1) {
    extern __shared__ float sm[];
    float* sX = sm;           // 32*128
    float* sW = sm + 4096;    // 128*128  sW[k][c] = W1[c*512 + k]
    const int tid = threadIdx.x, tx = tid & 15, ty = tid >> 4;
    const int n0 = blockIdx.x * 32;

#pragma unroll
    for (int m = 0; m < 4; ++m) {
        int f4 = tid + 256 * m;              // 0..1023
        int r = f4 >> 5, c4 = f4 & 31;
        *(float4*)(sX + r * 128 + c4 * 4) =
            *(const float4*)(node + (size_t)(n0 + r) * 128 + c4 * 4);
    }
#pragma unroll
    for (int m = 0; m < 16; ++m) {
        int idx = tid + 256 * m;             // 0..4095
        int c = idx & 127, k4 = idx >> 7;
        float4 v = *(const float4*)(W1 + (size_t)c * 512 + k4 * 4);
        sW[(k4 * 4 + 0) * 128 + c] = v.x;
        sW[(k4 * 4 + 1) * 128 + c] = v.y;
        sW[(k4 * 4 + 2) * 128 + c] = v.z;
        sW[(k4 * 4 + 3) * 128 + c] = v.w;
    }
    __syncthreads();

    float acc[2][8] = {};
#pragma unroll
    for (int kk = 0; kk < 128; kk += 4) {
        float a[2][4];
#pragma unroll
        for (int i = 0; i < 2; ++i) {
            float4 t = *(float4*)(sX + (ty + 16 * i) * 128 + kk);
            a[i][0] = t.x; a[i][1] = t.y; a[i][2] = t.z; a[i][3] = t.w;
        }
#pragma unroll
        for (int q = 0; q < 4; ++q) {
            float4 b0 = *(float4*)(sW + (kk + q) * 128 + tx * 8);
            float4 b1v = *(float4*)(sW + (kk + q) * 128 + tx * 8 + 4);
            float bb[8] = {b0.x, b0.y, b0.z, b0.w, b1v.x, b1v.y, b1v.z, b1v.w};
#pragma unroll
            for (int i = 0; i < 2; ++i)
#pragma unroll
                for (int j = 0; j < 8; ++j) acc[i][j] += a[i][q] * bb[j];
        }
    }
#pragma unroll
    for (int i = 0; i < 2; ++i) {
        int r = n0 + ty + 16 * i;
#pragma unroll
        for (int j = 0; j < 8; ++j) {
            int c = tx * 8 + j;
            g_node_pre[(size_t)r * 128 + c] = acc[i][j] + b1[c];
        }
    }
}

// ======================= K1: per-node edge message kernel ===================
// block = one node n. GEMM1b (48x384 @ 384x128) + gelu, GEMM2 (48x128 @ 128x128)
// + gelu, attn-weighted reduce over 48 -> g_S, g_A.
__global__ __launch_bounds__(256, 2)
void k1_edges(const float* __restrict__ edge, const float* __restrict__ attn,
              const float* __restrict__ W1, const float* __restrict__ W2,
              const float* __restrict__ b2) {
    extern __shared__ float sm[];
    float* sU = sm;                 // 16384 floats: union{sA,sB} / sB2
    float* sH = sm + 16384;         // 6144: h1 (48x128), later sPart
    float* sNP = sm + 16384 + 6144; // 128
    float* sAt = sNP + 128;         // 64 (48 used)
    float* sA = sU;                 // 48*64
    float* sB = sU + 3072;          // 64*128

    const int n = blockIdx.x;
    const int tid = threadIdx.x;
    const int tx = tid & 15;
    const int ty = tid >> 4;
    const float* eb = edge + (size_t)n * (KN * EC);

    if (tid < 128) sNP[tid] = g_node_pre[(size_t)n * 128 + tid];
    if (tid < KN) sAt[tid] = attn[(size_t)n * KN + tid];

    float acc[3][8] = {};

    // ---- GEMM1b over edge context, k-tiles of 64 ----
    for (int kt = 0; kt < 6; ++kt) {
        __syncthreads();
#pragma unroll
        for (int m = 0; m < 3; ++m) {
            int f4 = tid + 256 * m;          // 0..767
            int r = f4 >> 4, c4 = f4 & 15;
            *(float4*)(sA + r * 64 + c4 * 4) =
                *(const float4*)(eb + (size_t)r * EC + kt * 64 + c4 * 4);
        }
#pragma unroll
        for (int m = 0; m < 8; ++m) {
            int idx = tid + 256 * m;         // 0..2047
            int c = idx & 127, d4 = idx >> 7;
            float4 v = *(const float4*)(W1 + (size_t)c * 512 + 128 + kt * 64 + d4 * 4);
            sB[(d4 * 4 + 0) * 128 + c] = v.x;
            sB[(d4 * 4 + 1) * 128 + c] = v.y;
            sB[(d4 * 4 + 2) * 128 + c] = v.z;
            sB[(d4 * 4 + 3) * 128 + c] = v.w;
        }
        __syncthreads();
#pragma unroll
        for (int kk = 0; kk < 64; kk += 4) {
            float a[3][4];
#pragma unroll
            for (int i = 0; i < 3; ++i) {
                float4 t = *(float4*)(sA + (ty + 16 * i) * 64 + kk);
                a[i][0] = t.x; a[i][1] = t.y; a[i][2] = t.z; a[i][3] = t.w;
            }
#pragma unroll
            for (int q = 0; q < 4; ++q) {
                float4 b0 = *(float4*)(sB + (kk + q) * 128 + tx * 8);
                float4 b1v = *(float4*)(sB + (kk + q) * 128 + tx * 8 + 4);
                float bb[8] = {b0.x, b0.y, b0.z, b0.w, b1v.x, b1v.y, b1v.z, b1v.w};
#pragma unroll
                for (int i = 0; i < 3; ++i)
#pragma unroll
                    for (int j = 0; j < 8; ++j) acc[i][j] += a[i][q] * bb[j];
            }
        }
    }

    // ---- epilogue 1: h1 = gelu(node_pre + acc) -> sH ----
#pragma unroll
    for (int i = 0; i < 3; ++i) {
        int r = ty + 16 * i;
        float h[8];
#pragma unroll
        for (int j = 0; j < 8; ++j) h[j] = gelu_f(acc[i][j] + sNP[tx * 8 + j]);
        *(float4*)(sH + r * 128 + tx * 8) = make_float4(h[0], h[1], h[2], h[3]);
        *(float4*)(sH + r * 128 + tx * 8 + 4) = make_float4(h[4], h[5], h[6], h[7]);
    }
    __syncthreads();

    // ---- load W2^T into sU: sU[c][d] = W2[d*128 + c] ----
#pragma unroll
    for (int m = 0; m < 16; ++m) {
        int idx = tid + 256 * m;             // 0..4095
        int d = idx & 127, c4 = idx >> 7;
        float4 v = *(const float4*)(W2 + (size_t)d * 128 + c4 * 4);
        sU[(c4 * 4 + 0) * 128 + d] = v.x;
        sU[(c4 * 4 + 1) * 128 + d] = v.y;
        sU[(c4 * 4 + 2) * 128 + d] = v.z;
        sU[(c4 * 4 + 3) * 128 + d] = v.w;
    }
    __syncthreads();

    // ---- GEMM2: acc2 = h1 @ W2^T ----
    float acc2[3][8] = {};
#pragma unroll
    for (int kk = 0; kk < 128; kk += 4) {
        float a[3][4];
#pragma unroll
        for (int i = 0; i < 3; ++i) {
            float4 t = *(float4*)(sH + (ty + 16 * i) * 128 + kk);
            a[i][0] = t.x; a[i][1] = t.y; a[i][2] = t.z; a[i][3] = t.w;
        }
#pragma unroll
        for (int q = 0; q < 4; ++q) {
            float4 b0 = *(float4*)(sU + (kk + q) * 128 + tx * 8);
            float4 b1v = *(float4*)(sU + (kk + q) * 128 + tx * 8 + 4);
            float bb[8] = {b0.x, b0.y, b0.z, b0.w, b1v.x, b1v.y, b1v.z, b1v.w};
#pragma unroll
            for (int i = 0; i < 3; ++i)
#pragma unroll
                for (int j = 0; j < 8; ++j) acc2[i][j] += a[i][q] * bb[j];
        }
    }

    // ---- epilogue 2: h2 = gelu(acc2 + b2); weighted partial over rows ----
    float w0 = sAt[ty], w1 = sAt[ty + 16], w2 = sAt[ty + 32];
    float4 b2a = *(const float4*)(b2 + tx * 8);
    float4 b2b = *(const float4*)(b2 + tx * 8 + 4);
    float b2v[8] = {b2a.x, b2a.y, b2a.z, b2a.w, b2b.x, b2b.y, b2b.z, b2b.w};
    float part[8];
#pragma unroll
    for (int j = 0; j < 8; ++j) {
        float p0 = gelu_f(acc2[0][j] + b2v[j]);
        float p1 = gelu_f(acc2[1][j] + b2v[j]);
        float p2 = gelu_f(acc2[2][j] + b2v[j]);
        part[j] = w0 * p0 + w1 * p1 + w2 * p2;
    }
    __syncthreads();                 // all sH reads done -> reuse as sPart
    float* sPart = sH;               // 16 x 128
    *(float4*)(sPart + ty * 128 + tx * 8) = make_float4(part[0], part[1], part[2], part[3]);
    *(float4*)(sPart + ty * 128 + tx * 8 + 4) = make_float4(part[4], part[5], part[6], part[7]);
    __syncthreads();

    if (tid < 128) {
        float s = 0.f;
#pragma unroll
        for (int t = 0; t < 16; ++t) s += sPart[t * 128 + tid];
        g_S[(size_t)n * 128 + tid] = s;
    }
    if (tid == 0) {
        float s = 0.f;
#pragma unroll
        for (int k = 0; k < KN; ++k) s += sAt[k];
        g_A[n] = s;
    }
}

// ========= K2: x = LN1(node + (W3 @ S + A*b3)/30) -> g_X (fused) ===========
__global__ __launch_bounds__(256)
void k2_ln1(const float* __restrict__ node, const float* __restrict__ W3,
            const float* __restrict__ b3, const float* __restrict__ g1,
            const float* __restrict__ be1) {
    extern __shared__ float sm[];
    float* sS = sm;            // 32*128
    float* sW = sm + 4096;     // 128*128  sW[c][d] = W3[d*128 + c]
    float* sRs = sm + 20480;   // 512
    float* sRq = sm + 20992;   // 512
    const int tid = threadIdx.x, tx = tid & 15, ty = tid >> 4;
    const int n0 = blockIdx.x * 32;

#pragma unroll
    for (int m = 0; m < 4; ++m) {
        int f4 = tid + 256 * m;
        int r = f4 >> 5, c4 = f4 & 31;
        *(float4*)(sS + r * 128 + c4 * 4) =
            *(const float4*)(g_S + (size_t)(n0 + r) * 128 + c4 * 4);
    }
#pragma unroll
    for (int m = 0; m < 16; ++m) {
        int idx = tid + 256 * m;
        int d = idx & 127, c4 = idx >> 7;
        float4 v = *(const float4*)(W3 + (size_t)d * 128 + c4 * 4);
        sW[(c4 * 4 + 0) * 128 + d] = v.x;
        sW[(c4 * 4 + 1) * 128 + d] = v.y;
        sW[(c4 * 4 + 2) * 128 + d] = v.z;
        sW[(c4 * 4 + 3) * 128 + d] = v.w;
    }
    __syncthreads();

    float acc[2][8] = {};
#pragma unroll
    for (int kk = 0; kk < 128; kk += 4) {
        float a[2][4];
#pragma unroll
        for (int i = 0; i < 2; ++i) {
            float4 t = *(float4*)(sS + (ty + 16 * i) * 128 + kk);
            a[i][0] = t.x; a[i][1] = t.y; a[i][2] = t.z; a[i][3] = t.w;
        }
#pragma unroll
        for (int q = 0; q < 4; ++q) {
            float4 b0 = *(float4*)(sW + (kk + q) * 128 + tx * 8);
            float4 b1v = *(float4*)(sW + (kk + q) * 128 + tx * 8 + 4);
            float bb[8] = {b0.x, b0.y, b0.z, b0.w, b1v.x, b1v.y, b1v.z, b1v.w};
#pragma unroll
            for (int i = 0; i < 2; ++i)
#pragma unroll
                for (int j = 0; j < 8; ++j) acc[i][j] += a[i][q] * bb[j];
        }
    }

    float xv[2][8];
    float4 b30 = *(const float4*)(b3 + tx * 8);
    float4 b31 = *(const float4*)(b3 + tx * 8 + 4);
    float b3v[8] = {b30.x, b30.y, b30.z, b30.w, b31.x, b31.y, b31.z, b31.w};
#pragma unroll
    for (int i = 0; i < 2; ++i) {
        int r = ty + 16 * i, n = n0 + r;
        float As = g_A[n];
        float4 nv0 = *(const float4*)(node + (size_t)n * 128 + tx * 8);
        float4 nv1 = *(const float4*)(node + (size_t)n * 128 + tx * 8 + 4);
        float nb[8] = {nv0.x, nv0.y, nv0.z, nv0.w, nv1.x, nv1.y, nv1.z, nv1.w};
        float s = 0.f, q = 0.f;
#pragma unroll
        for (int j = 0; j < 8; ++j) {
            float v = nb[j] + (acc[i][j] + As * b3v[j]) * (1.0f / 30.0f);
            xv[i][j] = v; s += v; q += v * v;
        }
        sRs[r * 16 + tx] = s;
        sRq[r * 16 + tx] = q;
    }
    __syncthreads();
    float4 ga = *(const float4*)(g1 + tx * 8);
    float4 gb = *(const float4*)(g1 + tx * 8 + 4);
    float4 ea = *(const float4*)(be1 + tx * 8);
    float4 ebv = *(const float4*)(be1 + tx * 8 + 4);
    float gv[8] = {ga.x, ga.y, ga.z, ga.w, gb.x, gb.y, gb.z, gb.w};
    float ev[8] = {ea.x, ea.y, ea.z, ea.w, ebv.x, ebv.y, ebv.z, ebv.w};
#pragma unroll
    for (int i = 0; i < 2; ++i) {
        int r = ty + 16 * i;
        float s = 0.f, q = 0.f;
#pragma unroll
        for (int t = 0; t < 16; ++t) { s += sRs[r * 16 + t]; q += sRq[r * 16 + t]; }
        float mu = s * (1.0f / 128.0f);
        float var = q * (1.0f / 128.0f) - mu * mu;
        float rs = rsqrtf(var + 1e-5f);
        float o[8];
#pragma unroll
        for (int j = 0; j < 8; ++j) o[j] = (xv[i][j] - mu) * rs * gv[j] + ev[j];
        *(float4*)(g_X + (size_t)(n0 + r) * 128 + tx * 8) = make_float4(o[0], o[1], o[2], o[3]);
        *(float4*)(g_X + (size_t)(n0 + r) * 128 + tx * 8 + 4) = make_float4(o[4], o[5], o[6], o[7]);
    }
}

// ================= K3: g_H = gelu(g_X @ Wd1^T + bd1)  (N=512) ===============
__global__ __launch_bounds__(256)
void k3_mlp1(const float* __restrict__ Wd1, const float* __restrict__ bd1) {
    extern __shared__ float sm[];
    float* sX = sm;          // 32*128
    float* sW = sm + 4096;   // 128*128 per n-tile: sW[k][h] = Wd1[(h0+h)*128 + k]
    const int tid = threadIdx.x, tx = tid & 15, ty = tid >> 4;
    const int n0 = blockIdx.x * 32;

#pragma unroll
    for (int m = 0; m < 4; ++m) {
        int f4 = tid + 256 * m;
        int r = f4 >> 5, c4 = f4 & 31;
        *(float4*)(sX + r * 128 + c4 * 4) =
            *(const float4*)(g_X + (size_t)(n0 + r) * 128 + c4 * 4);
    }

    for (int h0 = 0; h0 < 512; h0 += 128) {
        __syncthreads();
#pragma unroll
        for (int m = 0; m < 16; ++m) {
            int idx = tid + 256 * m;
            int h = idx & 127, k4 = idx >> 7;
            float4 v = *(const float4*)(Wd1 + (size_t)(h0 + h) * 128 + k4 * 4);
            sW[(k4 * 4 + 0) * 128 + h] = v.x;
            sW[(k4 * 4 + 1) * 128 + h] = v.y;
            sW[(k4 * 4 + 2) * 128 + h] = v.z;
            sW[(k4 * 4 + 3) * 128 + h] = v.w;
        }
        __syncthreads();
        float acc[2][8] = {};
#pragma unroll
        for (int kk = 0; kk < 128; kk += 4) {
            float a[2][4];
#pragma unroll
            for (int i = 0; i < 2; ++i) {
                float4 t = *(float4*)(sX + (ty + 16 * i) * 128 + kk);
                a[i][0] = t.x; a[i][1] = t.y; a[i][2] = t.z; a[i][3] = t.w;
            }
#pragma unroll
            for (int q = 0; q < 4; ++q) {
                float4 b0 = *(float4*)(sW + (kk + q) * 128 + tx * 8);
                float4 b1v = *(float4*)(sW + (kk + q) * 128 + tx * 8 + 4);
                float bb[8] = {b0.x, b0.y, b0.z, b0.w, b1v.x, b1v.y, b1v.z, b1v.w};
#pragma unroll
                for (int i = 0; i < 2; ++i)
#pragma unroll
                    for (int j = 0; j < 8; ++j) acc[i][j] += a[i][q] * bb[j];
            }
        }
#pragma unroll
        for (int i = 0; i < 2; ++i) {
            int r = n0 + ty + 16 * i;
#pragma unroll
            for (int j = 0; j < 8; ++j) {
                int h = h0 + tx * 8 + j;
                g_H[(size_t)r * 512 + h] = gelu_f(acc[i][j] + bd1[h]);
            }
        }
    }
}

// ===== K4: out = mask * LN2(g_X + g_H @ Wd2^T + bd2)  (K=512, N=128) ========
__global__ __launch_bounds__(256)
void k4_out(const float* __restrict__ Wd2, const float* __restrict__ bd2,
            const float* __restrict__ g2, const float* __restrict__ be2,
            const float* __restrict__ maskp, float* __restrict__ out) {
    extern __shared__ float sm[];
    float* sA = sm;            // 32*128 (k-tile of g_H)
    float* sW = sm + 4096;     // 128*128: sW[k][c] = Wd2[c*512 + k0 + k]
    float* sRs = sm + 20480;   // 512
    float* sRq = sm + 20992;   // 512
    const int tid = threadIdx.x, tx = tid & 15, ty = tid >> 4;
    const int n0 = blockIdx.x * 32;

    float acc[2][8] = {};
    for (int k0 = 0; k0 < 512; k0 += 128) {
        __syncthreads();
#pragma unroll
        for (int m = 0; m < 4; ++m) {
            int f4 = tid + 256 * m;
            int r = f4 >> 5, c4 = f4 & 31;
            *(float4*)(sA + r * 128 + c4 * 4) =
                *(const float4*)(g_H + (size_t)(n0 + r) * 512 + k0 + c4 * 4);
        }
#pragma unroll
        for (int m = 0; m < 16; ++m) {
            int idx = tid + 256 * m;
            int c = idx & 127, k4 = idx >> 7;
            float4 v = *(const float4*)(Wd2 + (size_t)c * 512 + k0 + k4 * 4);
            sW[(k4 * 4 + 0) * 128 + c] = v.x;
            sW[(k4 * 4 + 1) * 128 + c] = v.y;
            sW[(k4 * 4 + 2) * 128 + c] = v.z;
            sW[(k4 * 4 + 3) * 128 + c] = v.w;
        }
        __syncthreads();
#pragma unroll
        for (int kk = 0; kk < 128; kk += 4) {
            float a[2][4];
#pragma unroll
            for (int i = 0; i < 2; ++i) {
                float4 t = *(float4*)(sA + (ty + 16 * i) * 128 + kk);
                a[i][0] = t.x; a[i][1] = t.y; a[i][2] = t.z; a[i][3] = t.w;
            }
#pragma unroll
            for (int q = 0; q < 4; ++q) {
                float4 b0 = *(float4*)(sW + (kk + q) * 128 + tx * 8);
                float4 b1v = *(float4*)(sW + (kk + q) * 128 + tx * 8 + 4);
                float bb[8] = {b0.x, b0.y, b0.z, b0.w, b1v.x, b1v.y, b1v.z, b1v.w};
#pragma unroll
                for (int i = 0; i < 2; ++i)
#pragma unroll
                    for (int j = 0; j < 8; ++j) acc[i][j] += a[i][q] * bb[j];
            }
        }
    }

    float xv[2][8];
    float4 ba = *(const float4*)(bd2 + tx * 8);
    float4 bbv = *(const float4*)(bd2 + tx * 8 + 4);
    float bdv[8] = {ba.x, ba.y, ba.z, ba.w, bbv.x, bbv.y, bbv.z, bbv.w};
#pragma unroll
    for (int i = 0; i < 2; ++i) {
        int r = ty + 16 * i, n = n0 + r;
        float4 x0 = *(const float4*)(g_X + (size_t)n * 128 + tx * 8);
        float4 x1 = *(const float4*)(g_X + (size_t)n * 128 + tx * 8 + 4);
        float xb[8] = {x0.x, x0.y, x0.z, x0.w, x1.x, x1.y, x1.z, x1.w};
        float s = 0.f, q = 0.f;
#pragma unroll
        for (int j = 0; j < 8; ++j) {
            float v = xb[j] + acc[i][j] + bdv[j];
            xv[i][j] = v; s += v; q += v * v;
        }
        sRs[r * 16 + tx] = s;
        sRq[r * 16 + tx] = q;
    }
    __syncthreads();
    float4 ga = *(const float4*)(g2 + tx * 8);
    float4 gb = *(const float4*)(g2 + tx * 8 + 4);
    float4 ea = *(const float4*)(be2 + tx * 8);
    float4 ebv = *(const float4*)(be2 + tx * 8 + 4);
    float gv[8] = {ga.x, ga.y, ga.z, ga.w, gb.x, gb.y, gb.z, gb.w};
    float ev[8] = {ea.x, ea.y, ea.z, ea.w, ebv.x, ebv.y, ebv.z, ebv.w};
#pragma unroll
    for (int i = 0; i < 2; ++i) {
        int r = ty + 16 * i, n = n0 + r;
        float s = 0.f, q = 0.f;
#pragma unroll
        for (int t = 0; t < 16; ++t) { s += sRs[r * 16 + t]; q += sRq[r * 16 + t]; }
        float mu = s * (1.0f / 128.0f);
        float var = q * (1.0f / 128.0f) - mu * mu;
        float rs = rsqrtf(var + 1e-5f);
        float mk = maskp[n];
        float o[8];
#pragma unroll
        for (int j = 0; j < 8; ++j)
            o[j] = mk * ((xv[i][j] - mu) * rs * gv[j] + ev[j]);
        *(float4*)(out + (size_t)n * 128 + tx * 8) = make_float4(o[0], o[1], o[2], o[3]);
        *(float4*)(out + (size_t)n * 128 + tx * 8 + 4) = make_float4(o[4], o[5], o[6], o[7]);
    }
}

// ============================== launch =====================================
extern "C" void kernel_launch(void* const* d_in, const int* in_sizes, int n_in,
                              void* d_out, int out_size) {
    const float* node = (const float*)d_in[0];
    const float* edge = (const float*)d_in[1];
    const float* mask = (const float*)d_in[2];
    const float* attn = (const float*)d_in[3];
    const float* W1   = (const float*)d_in[4];
    const float* b1   = (const float*)d_in[5];
    const float* W2   = (const float*)d_in[6];
    const float* b2   = (const float*)d_in[7];
    const float* W3   = (const float*)d_in[8];
    const float* b3   = (const float*)d_in[9];
    const float* g1   = (const float*)d_in[10];
    const float* be1  = (const float*)d_in[11];
    const float* Wd1  = (const float*)d_in[12];
    const float* bd1  = (const float*)d_in[13];
    const float* Wd2  = (const float*)d_in[14];
    const float* bd2  = (const float*)d_in[15];
    const float* g2   = (const float*)d_in[16];
    const float* be2  = (const float*)d_in[17];
    float* out = (float*)d_out;

    const size_t s0 = (size_t)(4096 + 16384) * sizeof(float);
    const size_t s1 = (size_t)(16384 + 6144 + 128 + 64) * sizeof(float);
    const size_t s2 = (size_t)(4096 + 16384 + 512 + 512) * sizeof(float);
    const size_t s3 = (size_t)(4096 + 16384) * sizeof(float);
    const size_t s4 = (size_t)(4096 + 16384 + 512 + 512) * sizeof(float);

    cudaFuncSetAttribute(k0_node_pre, cudaFuncAttributeMaxDynamicSharedMemorySize, (int)s0);
    cudaFuncSetAttribute(k1_edges,    cudaFuncAttributeMaxDynamicSharedMemorySize, (int)s1);
    cudaFuncSetAttribute(k2_ln1,      cudaFuncAttributeMaxDynamicSharedMemorySize, (int)s2);
    cudaFuncSetAttribute(k3_mlp1,     cudaFuncAttributeMaxDynamicSharedMemorySize, (int)s3);
    cudaFuncSetAttribute(k4_out,      cudaFuncAttributeMaxDynamicSharedMemorySize, (int)s4);

    k0_node_pre<<<NN / 32, 256, s0>>>(node, W1, b1);
    k1_edges<<<NN, 256, s1>>>(edge, attn, W1, W2, b2);
    k2_ln1<<<NN / 32, 256, s2>>>(node, W3, b3, g1, be1);
    k3_mlp1<<<NN / 32, 256, s3>>>(Wd1, bd1);
    k4_out<<<NN / 32, 256, s4>>>(Wd2, bd2, g2, be2, mask, out);
}

// round 8
// speedup vs baseline: 5.0005x; 4.9921x over previous
#include <cuda_runtime.h>
#include <cuda_bf16.h>
#include <math.h>

#define NN 4096
#define KN 48
#define CC 128
#define EC 384
#define HD 512

// ---------------- scratch (device globals: allocation-free) ----------------
__device__ float g_node_pre[NN * CC];   // node @ W1a^T + b_m1
__device__ float g_S[NN * CC];          // sum_k attn * h2
__device__ float g_A[NN];               // sum_k attn
__device__ float g_X[NN * CC];          // post-LN1 x
__device__ float g_H[NN * HD];          // gelu(x @ Wd1^T + bd1)
__device__ unsigned g_Wp1[192 * 128];   // W1b^T packed bf16x2 along k: [kk][c]
__device__ unsigned g_Wp2[64 * 128];    // W2^T  packed bf16x2 along k: [kk][c]

__device__ __forceinline__ float gelu_f(float x) {
    return 0.5f * x * (1.0f + erff(x * 0.70710678118654752440f));
}

__device__ __forceinline__ unsigned pk(float a, float b) {
    __nv_bfloat162 t = __floats2bfloat162_rn(a, b);
    return *(unsigned*)&t;
}

__device__ __forceinline__ void mma_bf16(float c[4], const unsigned a[4], const unsigned b[2]) {
    asm volatile(
        "mma.sync.aligned.m16n8k16.row.col.f32.bf16.bf16.f32 "
        "{%0,%1,%2,%3},{%4,%5,%6,%7},{%8,%9},{%0,%1,%2,%3};\n"
        : "+f"(c[0]), "+f"(c[1]), "+f"(c[2]), "+f"(c[3])
        : "r"(a[0]), "r"(a[1]), "r"(a[2]), "r"(a[3]), "r"(b[0]), "r"(b[1]));
}

// =================== Kprep: pack weights to bf16x2 =========================
__global__ __launch_bounds__(256)
void k_prep(const float* __restrict__ W1, const float* __restrict__ W2) {
    int idx = blockIdx.x * 256 + threadIdx.x;
    if (idx < 192 * 128) {
        int kk = idx >> 7, c = idx & 127;
        g_Wp1[idx] = pk(W1[(size_t)c * 512 + 128 + 2 * kk],
                        W1[(size_t)c * 512 + 128 + 2 * kk + 1]);
    } else if (idx < 192 * 128 + 64 * 128) {
        int j = idx - 192 * 128;
        int kk = j >> 7, c = j & 127;
        g_Wp2[j] = pk(W2[(size_t)c * 128 + 2 * kk],
                      W2[(size_t)c * 128 + 2 * kk + 1]);
    }
}

// ======================= K0: node_pre = node @ W1a^T + b1 ==================
__global__ __launch_bounds__(256)
void k0_node_pre(const float* __restrict__ node, const float* __restrict__ W1,
                 const float* __restrict__ b1) {
    extern __shared__ float sm[];
    float* sX = sm;           // 32*128
    float* sW = sm + 4096;    // 128*128  sW[k][c] = W1[c*512 + k]
    const int tid = threadIdx.x, tx = tid & 15, ty = tid >> 4;
    const int n0 = blockIdx.x * 32;

#pragma unroll
    for (int m = 0; m < 4; ++m) {
        int f4 = tid + 256 * m;
        int r = f4 >> 5, c4 = f4 & 31;
        *(float4*)(sX + r * 128 + c4 * 4) =
            *(const float4*)(node + (size_t)(n0 + r) * 128 + c4 * 4);
    }
#pragma unroll
    for (int m = 0; m < 16; ++m) {
        int idx = tid + 256 * m;
        int c = idx & 127, k4 = idx >> 7;
        float4 v = *(const float4*)(W1 + (size_t)c * 512 + k4 * 4);
        sW[(k4 * 4 + 0) * 128 + c] = v.x;
        sW[(k4 * 4 + 1) * 128 + c] = v.y;
        sW[(k4 * 4 + 2) * 128 + c] = v.z;
        sW[(k4 * 4 + 3) * 128 + c] = v.w;
    }
    __syncthreads();

    float acc[2][8] = {};
#pragma unroll
    for (int kk = 0; kk < 128; kk += 4) {
        float a[2][4];
#pragma unroll
        for (int i = 0; i < 2; ++i) {
            float4 t = *(float4*)(sX + (ty + 16 * i) * 128 + kk);
            a[i][0] = t.x; a[i][1] = t.y; a[i][2] = t.z; a[i][3] = t.w;
        }
#pragma unroll
        for (int q = 0; q < 4; ++q) {
            float4 b0 = *(float4*)(sW + (kk + q) * 128 + tx * 8);
            float4 b1v = *(float4*)(sW + (kk + q) * 128 + tx * 8 + 4);
            float bb[8] = {b0.x, b0.y, b0.z, b0.w, b1v.x, b1v.y, b1v.z, b1v.w};
#pragma unroll
            for (int i = 0; i < 2; ++i)
#pragma unroll
                for (int j = 0; j < 8; ++j) acc[i][j] += a[i][q] * bb[j];
        }
    }
#pragma unroll
    for (int i = 0; i < 2; ++i) {
        int r = n0 + ty + 16 * i;
#pragma unroll
        for (int j = 0; j < 8; ++j) {
            int c = tx * 8 + j;
            g_node_pre[(size_t)r * 128 + c] = acc[i][j] + b1[c];
        }
    }
}

// ================ K1: per-node-pair edge message kernel (bf16 MMA) =========
// Block handles 2 nodes (96 edge rows). 8 warps = 2 (node) x 4 (n32 cols).
// GEMM1b: 96x384 @ 384x128 (bf16 HMMA) + gelu -> sH (bf16x2)
// GEMM2:  96x128 @ 128x128 (bf16 HMMA) + gelu, attn-weighted 48-row reduce.
#define SA_OFF 0            // 96 * 36 u32 (edge tile, bf16x2, pad 36)
#define SB_OFF 3456         // 64 * 136 u32 (weight tile, bf16x2, pad 136)
#define SH_OFF 12160        // 96 * 68 u32 (h1 bf16x2, pad 68)
#define SNP_OFF 18688       // 256 f (node_pre, 2 nodes)
#define SAT_OFF 18944       // 96 f (attn)
#define SB2_OFF 19040       // 128 f (b2)
#define S1_WORDS 19168

__global__ __launch_bounds__(256, 2)
void k1_edges(const float* __restrict__ edge, const float* __restrict__ attn,
              const float* __restrict__ b2) {
    extern __shared__ unsigned smu[];
    unsigned* sA = smu + SA_OFF;
    unsigned* sB = smu + SB_OFF;
    unsigned* sH = smu + SH_OFF;
    float* sNP = (float*)(smu + SNP_OFF);
    float* sAt = (float*)(smu + SAT_OFF);
    float* sb2 = (float*)(smu + SB2_OFF);

    const int tid = threadIdx.x;
    const int lane = tid & 31, wid = tid >> 5;
    const int mg = wid >> 2;        // node within block (0,1)
    const int ng = wid & 3;         // n32 column group
    const int g = lane >> 2, q = lane & 3;
    const int n0 = blockIdx.x * 2;
    const float* eb = edge + (size_t)n0 * (KN * EC);

    if (tid < 256) sNP[tid] = g_node_pre[(size_t)n0 * 128 + tid];
    if (tid < 96) sAt[tid] = attn[(size_t)n0 * KN + tid];
    if (tid < 128) sb2[tid] = b2[tid];

    float acc[3][4][4] = {};

    // ---------------- GEMM1b over edge context: 6 k-tiles of 64 ------------
    for (int kt = 0; kt < 6; ++kt) {
        // A: 96 rows x 64 fp32 -> bf16x2 packed (1536 float4 / 256 thr = 6)
#pragma unroll
        for (int m = 0; m < 6; ++m) {
            int f = tid + 256 * m;
            int row = f >> 4, c4 = f & 15;
            float4 v = *(const float4*)(eb + (size_t)row * EC + kt * 64 + c4 * 4);
            *(uint2*)(sA + row * 36 + c4 * 2) =
                make_uint2(pk(v.x, v.y), pk(v.z, v.w));
        }
        // B: 32 kk-rows x 128 u32 (1024 uint4 / 256 = 4)
#pragma unroll
        for (int m = 0; m < 4; ++m) {
            int f = tid + 256 * m;
            int kk = f >> 5, c4 = f & 31;
            *(uint4*)(sB + kk * 136 + c4 * 4) =
                *(const uint4*)(g_Wp1 + (size_t)(kt * 32 + kk) * 128 + c4 * 4);
        }
        __syncthreads();
#pragma unroll
        for (int s = 0; s < 4; ++s) {
            unsigned a[3][4], bf[4][2];
#pragma unroll
            for (int mi = 0; mi < 3; ++mi) {
                const unsigned* base = sA + (mg * 48 + mi * 16 + g) * 36 + s * 8 + q;
                a[mi][0] = base[0];
                a[mi][1] = base[8 * 36];
                a[mi][2] = base[4];
                a[mi][3] = base[8 * 36 + 4];
            }
#pragma unroll
            for (int t = 0; t < 4; ++t) {
                int n = ng * 32 + t * 8 + g;
                bf[t][0] = sB[(s * 8 + q) * 136 + n];
                bf[t][1] = sB[(s * 8 + 4 + q) * 136 + n];
            }
#pragma unroll
            for (int mi = 0; mi < 3; ++mi)
#pragma unroll
                for (int t = 0; t < 4; ++t) mma_bf16(acc[mi][t], a[mi], bf[t]);
        }
        __syncthreads();
    }

    // ---- epilogue 1: h1 = gelu(node_pre + acc) -> sH (bf16x2) -------------
#pragma unroll
    for (int mi = 0; mi < 3; ++mi) {
        int r0 = mg * 48 + mi * 16 + g;
#pragma unroll
        for (int t = 0; t < 4; ++t) {
            int c = ng * 32 + t * 8 + 2 * q;
            float np0 = sNP[mg * 128 + c], np1 = sNP[mg * 128 + c + 1];
            unsigned lo = pk(gelu_f(acc[mi][t][0] + np0), gelu_f(acc[mi][t][1] + np1));
            unsigned hi = pk(gelu_f(acc[mi][t][2] + np0), gelu_f(acc[mi][t][3] + np1));
            sH[r0 * 68 + ng * 16 + t * 4 + q] = lo;
            sH[(r0 + 8) * 68 + ng * 16 + t * 4 + q] = hi;
            acc[mi][t][0] = acc[mi][t][1] = acc[mi][t][2] = acc[mi][t][3] = 0.f;
        }
    }
    __syncthreads();

    // ---- load W2^T packed into sB (64 kk x 128; 2048 uint4 / 256 = 8) -----
#pragma unroll
    for (int m = 0; m < 8; ++m) {
        int f = tid + 256 * m;
        int kk = f >> 5, c4 = f & 31;
        *(uint4*)(sB + kk * 136 + c4 * 4) =
            *(const uint4*)(g_Wp2 + (size_t)kk * 128 + c4 * 4);
    }
    if (tid < 2) {
        float s = 0.f;
#pragma unroll
        for (int k = 0; k < KN; ++k) s += sAt[tid * KN + k];
        g_A[n0 + tid] = s;
    }
    __syncthreads();

    // ---------------- GEMM2: h1 @ W2^T (8 k16 steps) -----------------------
#pragma unroll
    for (int s = 0; s < 8; ++s) {
        unsigned a[3][4], bf[4][2];
#pragma unroll
        for (int mi = 0; mi < 3; ++mi) {
            const unsigned* base = sH + (mg * 48 + mi * 16 + g) * 68 + s * 8 + q;
            a[mi][0] = base[0];
            a[mi][1] = base[8 * 68];
            a[mi][2] = base[4];
            a[mi][3] = base[8 * 68 + 4];
        }
#pragma unroll
        for (int t = 0; t < 4; ++t) {
            int n = ng * 32 + t * 8 + g;
            bf[t][0] = sB[(s * 8 + q) * 136 + n];
            bf[t][1] = sB[(s * 8 + 4 + q) * 136 + n];
        }
#pragma unroll
        for (int mi = 0; mi < 3; ++mi)
#pragma unroll
            for (int t = 0; t < 4; ++t) mma_bf16(acc[mi][t], a[mi], bf[t]);
    }

    // ---- epilogue 2: gelu(+b2), attn-weighted reduce over the 48 rows -----
#pragma unroll
    for (int t = 0; t < 4; ++t) {
        int c = ng * 32 + t * 8 + 2 * q;
        float bc0 = sb2[c], bc1 = sb2[c + 1];
        float p0 = 0.f, p1 = 0.f;
#pragma unroll
        for (int mi = 0; mi < 3; ++mi) {
            int r0 = mi * 16 + g;
            float w0 = sAt[mg * 48 + r0];
            float w1 = sAt[mg * 48 + r0 + 8];
            p0 += w0 * gelu_f(acc[mi][t][0] + bc0) + w1 * gelu_f(acc[mi][t][2] + bc0);
            p1 += w0 * gelu_f(acc[mi][t][1] + bc1) + w1 * gelu_f(acc[mi][t][3] + bc1);
        }
#pragma unroll
        for (int off = 16; off >= 4; off >>= 1) {
            p0 += __shfl_xor_sync(0xffffffffu, p0, off);
            p1 += __shfl_xor_sync(0xffffffffu, p1, off);
        }
        if (lane < 4) {
            int cc = ng * 32 + t * 8 + 2 * lane;
            g_S[(size_t)(n0 + mg) * 128 + cc] = p0;
            g_S[(size_t)(n0 + mg) * 128 + cc + 1] = p1;
        }
    }
}

// ========= K2: x = LN1(node + (W3 @ S + A*b3)/30) -> g_X (fused) ===========
__global__ __launch_bounds__(256)
void k2_ln1(const float* __restrict__ node, const float* __restrict__ W3,
            const float* __restrict__ b3, const float* __restrict__ g1,
            const float* __restrict__ be1) {
    extern __shared__ float sm[];
    float* sS = sm;            // 32*128
    float* sW = sm + 4096;     // 128*128  sW[c][d] = W3[d*128 + c]
    float* sRs = sm + 20480;   // 512
    float* sRq = sm + 20992;   // 512
    const int tid = threadIdx.x, tx = tid & 15, ty = tid >> 4;
    const int n0 = blockIdx.x * 32;

#pragma unroll
    for (int m = 0; m < 4; ++m) {
        int f4 = tid + 256 * m;
        int r = f4 >> 5, c4 = f4 & 31;
        *(float4*)(sS + r * 128 + c4 * 4) =
            *(const float4*)(g_S + (size_t)(n0 + r) * 128 + c4 * 4);
    }
#pragma unroll
    for (int m = 0; m < 16; ++m) {
        int idx = tid + 256 * m;
        int d = idx & 127, c4 = idx >> 7;
        float4 v = *(const float4*)(W3 + (size_t)d * 128 + c4 * 4);
        sW[(c4 * 4 + 0) * 128 + d] = v.x;
        sW[(c4 * 4 + 1) * 128 + d] = v.y;
        sW[(c4 * 4 + 2) * 128 + d] = v.z;
        sW[(c4 * 4 + 3) * 128 + d] = v.w;
    }
    __syncthreads();

    float acc[2][8] = {};
#pragma unroll
    for (int kk = 0; kk < 128; kk += 4) {
        float a[2][4];
#pragma unroll
        for (int i = 0; i < 2; ++i) {
            float4 t = *(float4*)(sS + (ty + 16 * i) * 128 + kk);
            a[i][0] = t.x; a[i][1] = t.y; a[i][2] = t.z; a[i][3] = t.w;
        }
#pragma unroll
        for (int q = 0; q < 4; ++q) {
            float4 b0 = *(float4*)(sW + (kk + q) * 128 + tx * 8);
            float4 b1v = *(float4*)(sW + (kk + q) * 128 + tx * 8 + 4);
            float bb[8] = {b0.x, b0.y, b0.z, b0.w, b1v.x, b1v.y, b1v.z, b1v.w};
#pragma unroll
            for (int i = 0; i < 2; ++i)
#pragma unroll
                for (int j = 0; j < 8; ++j) acc[i][j] += a[i][q] * bb[j];
        }
    }

    float xv[2][8];
    float4 b30 = *(const float4*)(b3 + tx * 8);
    float4 b31 = *(const float4*)(b3 + tx * 8 + 4);
    float b3v[8] = {b30.x, b30.y, b30.z, b30.w, b31.x, b31.y, b31.z, b31.w};
#pragma unroll
    for (int i = 0; i < 2; ++i) {
        int r = ty + 16 * i, n = n0 + r;
        float As = g_A[n];
        float4 nv0 = *(const float4*)(node + (size_t)n * 128 + tx * 8);
        float4 nv1 = *(const float4*)(node + (size_t)n * 128 + tx * 8 + 4);
        float nb[8] = {nv0.x, nv0.y, nv0.z, nv0.w, nv1.x, nv1.y, nv1.z, nv1.w};
        float s = 0.f, qq = 0.f;
#pragma unroll
        for (int j = 0; j < 8; ++j) {
            float v = nb[j] + (acc[i][j] + As * b3v[j]) * (1.0f / 30.0f);
            xv[i][j] = v; s += v; qq += v * v;
        }
        sRs[r * 16 + tx] = s;
        sRq[r * 16 + tx] = qq;
    }
    __syncthreads();
    float4 ga = *(const float4*)(g1 + tx * 8);
    float4 gb = *(const float4*)(g1 + tx * 8 + 4);
    float4 ea = *(const float4*)(be1 + tx * 8);
    float4 ebv = *(const float4*)(be1 + tx * 8 + 4);
    float gv[8] = {ga.x, ga.y, ga.z, ga.w, gb.x, gb.y, gb.z, gb.w};
    float ev[8] = {ea.x, ea.y, ea.z, ea.w, ebv.x, ebv.y, ebv.z, ebv.w};
#pragma unroll
    for (int i = 0; i < 2; ++i) {
        int r = ty + 16 * i;
        float s = 0.f, qq = 0.f;
#pragma unroll
        for (int t = 0; t < 16; ++t) { s += sRs[r * 16 + t]; qq += sRq[r * 16 + t]; }
        float mu = s * (1.0f / 128.0f);
        float var = qq * (1.0f / 128.0f) - mu * mu;
        float rs = rsqrtf(var + 1e-5f);
        float o[8];
#pragma unroll
        for (int j = 0; j < 8; ++j) o[j] = (xv[i][j] - mu) * rs * gv[j] + ev[j];
        *(float4*)(g_X + (size_t)(n0 + r) * 128 + tx * 8) = make_float4(o[0], o[1], o[2], o[3]);
        *(float4*)(g_X + (size_t)(n0 + r) * 128 + tx * 8 + 4) = make_float4(o[4], o[5], o[6], o[7]);
    }
}

// ============ K3: g_H = gelu(g_X @ Wd1^T + bd1)  (split over 4 h-tiles) ====
__global__ __launch_bounds__(256)
void k3_mlp1(const float* __restrict__ Wd1, const float* __restrict__ bd1) {
    extern __shared__ float sm[];
    float* sX = sm;          // 32*128
    float* sW = sm + 4096;   // 128*128: sW[k][h] = Wd1[(h0+h)*128 + k]
    const int tid = threadIdx.x, tx = tid & 15, ty = tid >> 4;
    const int n0 = blockIdx.x * 32;
    const int h0 = blockIdx.y * 128;

#pragma unroll
    for (int m = 0; m < 4; ++m) {
        int f4 = tid + 256 * m;
        int r = f4 >> 5, c4 = f4 & 31;
        *(float4*)(sX + r * 128 + c4 * 4) =
            *(const float4*)(g_X + (size_t)(n0 + r) * 128 + c4 * 4);
    }
#pragma unroll
    for (int m = 0; m < 16; ++m) {
        int idx = tid + 256 * m;
        int h = idx & 127, k4 = idx >> 7;
        float4 v = *(const float4*)(Wd1 + (size_t)(h0 + h) * 128 + k4 * 4);
        sW[(k4 * 4 + 0) * 128 + h] = v.x;
        sW[(k4 * 4 + 1) * 128 + h] = v.y;
        sW[(k4 * 4 + 2) * 128 + h] = v.z;
        sW[(k4 * 4 + 3) * 128 + h] = v.w;
    }
    __syncthreads();
    float acc[2][8] = {};
#pragma unroll
    for (int kk = 0; kk < 128; kk += 4) {
        float a[2][4];
#pragma unroll
        for (int i = 0; i < 2; ++i) {
            float4 t = *(float4*)(sX + (ty + 16 * i) * 128 + kk);
            a[i][0] = t.x; a[i][1] = t.y; a[i][2] = t.z; a[i][3] = t.w;
        }
#pragma unroll
        for (int q = 0; q < 4; ++q) {
            float4 b0 = *(float4*)(sW + (kk + q) * 128 + tx * 8);
            float4 b1v = *(float4*)(sW + (kk + q) * 128 + tx * 8 + 4);
            float bb[8] = {b0.x, b0.y, b0.z, b0.w, b1v.x, b1v.y, b1v.z, b1v.w};
#pragma unroll
            for (int i = 0; i < 2; ++i)
#pragma unroll
                for (int j = 0; j < 8; ++j) acc[i][j] += a[i][q] * bb[j];
        }
    }
#pragma unroll
    for (int i = 0; i < 2; ++i) {
        int r = n0 + ty + 16 * i;
#pragma unroll
        for (int j = 0; j < 8; ++j) {
            int h = h0 + tx * 8 + j;
            g_H[(size_t)r * 512 + h] = gelu_f(acc[i][j] + bd1[h]);
        }
    }
}

// ===== K4: out = mask * LN2(g_X + g_H @ Wd2^T + bd2)  (K=512, N=128) ========
__global__ __launch_bounds__(256)
void k4_out(const float* __restrict__ Wd2, const float* __restrict__ bd2,
            const float* __restrict__ g2, const float* __restrict__ be2,
            const float* __restrict__ maskp, float* __restrict__ out) {
    extern __shared__ float sm[];
    float* sA = sm;            // 32*128 (k-tile of g_H)
    float* sW = sm + 4096;     // 128*128: sW[k][c] = Wd2[c*512 + k0 + k]
    float* sRs = sm + 20480;   // 512
    float* sRq = sm + 20992;   // 512
    const int tid = threadIdx.x, tx = tid & 15, ty = tid >> 4;
    const int n0 = blockIdx.x * 32;

    float acc[2][8] = {};
    for (int k0 = 0; k0 < 512; k0 += 128) {
        __syncthreads();
#pragma unroll
        for (int m = 0; m < 4; ++m) {
            int f4 = tid + 256 * m;
            int r = f4 >> 5, c4 = f4 & 31;
            *(float4*)(sA + r * 128 + c4 * 4) =
                *(const float4*)(g_H + (size_t)(n0 + r) * 512 + k0 + c4 * 4);
        }
#pragma unroll
        for (int m = 0; m < 16; ++m) {
            int idx = tid + 256 * m;
            int c = idx & 127, k4 = idx >> 7;
            float4 v = *(const float4*)(Wd2 + (size_t)c * 512 + k0 + k4 * 4);
            sW[(k4 * 4 + 0) * 128 + c] = v.x;
            sW[(k4 * 4 + 1) * 128 + c] = v.y;
            sW[(k4 * 4 + 2) * 128 + c] = v.z;
            sW[(k4 * 4 + 3) * 128 + c] = v.w;
        }
        __syncthreads();
#pragma unroll
        for (int kk = 0; kk < 128; kk += 4) {
            float a[2][4];
#pragma unroll
            for (int i = 0; i < 2; ++i) {
                float4 t = *(float4*)(sA + (ty + 16 * i) * 128 + kk);
                a[i][0] = t.x; a[i][1] = t.y; a[i][2] = t.z; a[i][3] = t.w;
            }
#pragma unroll
            for (int q = 0; q < 4; ++q) {
                float4 b0 = *(float4*)(sW + (kk + q) * 128 + tx * 8);
                float4 b1v = *(float4*)(sW + (kk + q) * 128 + tx * 8 + 4);
                float bb[8] = {b0.x, b0.y, b0.z, b0.w, b1v.x, b1v.y, b1v.z, b1v.w};
#pragma unroll
                for (int i = 0; i < 2; ++i)
#pragma unroll
                    for (int j = 0; j < 8; ++j) acc[i][j] += a[i][q] * bb[j];
            }
        }
    }

    float xv[2][8];
    float4 ba = *(const float4*)(bd2 + tx * 8);
    float4 bbv = *(const float4*)(bd2 + tx * 8 + 4);
    float bdv[8] = {ba.x, ba.y, ba.z, ba.w, bbv.x, bbv.y, bbv.z, bbv.w};
#pragma unroll
    for (int i = 0; i < 2; ++i) {
        int r = ty + 16 * i, n = n0 + r;
        float4 x0 = *(const float4*)(g_X + (size_t)n * 128 + tx * 8);
        float4 x1 = *(const float4*)(g_X + (size_t)n * 128 + tx * 8 + 4);
        float xb[8] = {x0.x, x0.y, x0.z, x0.w, x1.x, x1.y, x1.z, x1.w};
        float s = 0.f, qq = 0.f;
#pragma unroll
        for (int j = 0; j < 8; ++j) {
            float v = xb[j] + acc[i][j] + bdv[j];
            xv[i][j] = v; s += v; qq += v * v;
        }
        sRs[r * 16 + tx] = s;
        sRq[r * 16 + tx] = qq;
    }
    __syncthreads();
    float4 ga = *(const float4*)(g2 + tx * 8);
    float4 gb = *(const float4*)(g2 + tx * 8 + 4);
    float4 ea = *(const float4*)(be2 + tx * 8);
    float4 ebv = *(const float4*)(be2 + tx * 8 + 4);
    float gv[8] = {ga.x, ga.y, ga.z, ga.w, gb.x, gb.y, gb.z, gb.w};
    float ev[8] = {ea.x, ea.y, ea.z, ea.w, ebv.x, ebv.y, ebv.z, ebv.w};
#pragma unroll
    for (int i = 0; i < 2; ++i) {
        int r = ty + 16 * i, n = n0 + r;
        float s = 0.f, qq = 0.f;
#pragma unroll
        for (int t = 0; t < 16; ++t) { s += sRs[r * 16 + t]; qq += sRq[r * 16 + t]; }
        float mu = s * (1.0f / 128.0f);
        float var = qq * (1.0f / 128.0f) - mu * mu;
        float rs = rsqrtf(var + 1e-5f);
        float mk = maskp[n];
        float o[8];
#pragma unroll
        for (int j = 0; j < 8; ++j)
            o[j] = mk * ((xv[i][j] - mu) * rs * gv[j] + ev[j]);
        *(float4*)(out + (size_t)n * 128 + tx * 8) = make_float4(o[0], o[1], o[2], o[3]);
        *(float4*)(out + (size_t)n * 128 + tx * 8 + 4) = make_float4(o[4], o[5], o[6], o[7]);
    }
}

// ============================== launch =====================================
extern "C" void kernel_launch(void* const* d_in, const int* in_sizes, int n_in,
                              void* d_out, int out_size) {
    const float* node = (const float*)d_in[0];
    const float* edge = (const float*)d_in[1];
    const float* mask = (const float*)d_in[2];
    const float* attn = (const float*)d_in[3];
    const float* W1   = (const float*)d_in[4];
    const float* b1   = (const float*)d_in[5];
    const float* W2   = (const float*)d_in[6];
    const float* b2   = (const float*)d_in[7];
    const float* W3   = (const float*)d_in[8];
    const float* b3   = (const float*)d_in[9];
    const float* g1   = (const float*)d_in[10];
    const float* be1  = (const float*)d_in[11];
    const float* Wd1  = (const float*)d_in[12];
    const float* bd1  = (const float*)d_in[13];
    const float* Wd2  = (const float*)d_in[14];
    const float* bd2  = (const float*)d_in[15];
    const float* g2   = (const float*)d_in[16];
    const float* be2  = (const float*)d_in[17];
    float* out = (float*)d_out;

    const size_t s0 = (size_t)(4096 + 16384) * sizeof(float);
    const size_t s1 = (size_t)S1_WORDS * sizeof(unsigned);
    const size_t s2 = (size_t)(4096 + 16384 + 512 + 512) * sizeof(float);
    const size_t s3 = (size_t)(4096 + 16384) * sizeof(float);
    const size_t s4 = (size_t)(4096 + 16384 + 512 + 512) * sizeof(float);

    cudaFuncSetAttribute(k0_node_pre, cudaFuncAttributeMaxDynamicSharedMemorySize, (int)s0);
    cudaFuncSetAttribute(k1_edges,    cudaFuncAttributeMaxDynamicSharedMemorySize, (int)s1);
    cudaFuncSetAttribute(k2_ln1,      cudaFuncAttributeMaxDynamicSharedMemorySize, (int)s2);
    cudaFuncSetAttribute(k3_mlp1,     cudaFuncAttributeMaxDynamicSharedMemorySize, (int)s3);
    cudaFuncSetAttribute(k4_out,      cudaFuncAttributeMaxDynamicSharedMemorySize, (int)s4);

    k_prep<<<128, 256>>>(W1, W2);
    k0_node_pre<<<NN / 32, 256, s0>>>(node, W1, b1);
    k1_edges<<<NN / 2, 256, s1>>>(edge, attn, b2);
    k2_ln1<<<NN / 32, 256, s2>>>(node, W3, b3, g1, be1);
    k3_mlp1<<<dim3(NN / 32, 4), 256, s3>>>(Wd1, bd1);
    k4_out<<<NN / 32, 256, s4>>>(Wd2, bd2, g2, be2, mask, out);
}